// round 12
// baseline (speedup 1.0000x reference)
#include <cuda_runtime.h>
#include <cuda_bf16.h>
#include <cuda_fp16.h>
#include <stdint.h>
#include <math.h>

#define NN 100000
#define NE 1600000
#define DD 128
#define SCAN_BLK 1024
#define NSB ((NN + SCAN_BLK - 1) / SCAN_BLK)   // 98 scan blocks
#define NTILES ((NN + 127) / 128)              // 782
#define MLP_GRID 304

// ---------------- scratch (device globals; no allocation) ----------------
__device__ alignas(16) __half g_agg16[(size_t)NN * DD];       // 25.6 MB (fp16 MLP input)
__device__ alignas(16) __half g_x16[(size_t)NN * DD];         // 25.6 MB (fp16 input copy)
__device__ alignas(16) __half g_xs16[(size_t)2 * NN * DD];    // 51.2 MB (fp16 layer0/1 outputs)
__device__ alignas(16) __nv_bfloat16 g_wb[6 * 128 * 256];     // split weights [mat][n][k: hi|lo]
__device__ alignas(16) int   g_deg[NN];
__device__ alignas(16) int   g_cur[NN];
__device__ alignas(16) int   g_srcs[NE];
__device__ alignas(16) int   g_off[NN + 1];
__device__ alignas(16) int   g_bsum[NSB];
__device__ alignas(16) int   g_bpre[NSB];
__device__ int g_is64;

__device__ __forceinline__ uint32_t smem_u32(const void* p) {
    uint32_t a;
    asm("{ .reg .u64 t; cvta.to.shared.u64 t, %1; cvt.u32.u64 %0, t; }" : "=r"(a) : "l"(p));
    return a;
}
__device__ __forceinline__ uint32_t pack_bf16(float a, float b) {
    __nv_bfloat16 ha = __float2bfloat16(a), hb = __float2bfloat16(b);
    return (uint32_t)__bfloat16_as_ushort(ha) | ((uint32_t)__bfloat16_as_ushort(hb) << 16);
}
__device__ __forceinline__ void ldsm4(uint32_t& r0, uint32_t& r1, uint32_t& r2, uint32_t& r3, uint32_t addr) {
    asm volatile("ldmatrix.sync.aligned.m8n8.x4.shared.b16 {%0,%1,%2,%3}, [%4];"
                 : "=r"(r0), "=r"(r1), "=r"(r2), "=r"(r3) : "r"(addr));
}
__device__ __forceinline__ void mma16816(float* c, const uint32_t* a, const uint32_t* b) {
    asm volatile("mma.sync.aligned.m16n8k16.row.col.f32.bf16.bf16.f32 "
                 "{%0,%1,%2,%3}, {%4,%5,%6,%7}, {%8,%9}, {%0,%1,%2,%3};"
                 : "+f"(c[0]), "+f"(c[1]), "+f"(c[2]), "+f"(c[3])
                 : "r"(a[0]), "r"(a[1]), "r"(a[2]), "r"(a[3]), "r"(b[0]), "r"(b[1]));
}
// swizzled smem byte offset within a 512B bf16 row (k: hi bytes 0-255, lo 256-511)
__device__ __forceinline__ uint32_t sws(int row, int kb) {
    return (uint32_t)(row * 512 + (kb ^ ((row & 7) << 4)));
}
// unpack 4 packed halves (uint2) -> float4
__device__ __forceinline__ float4 h4tof4(uint2 u) {
    __half2 h0 = *(__half2*)&u.x, h1 = *(__half2*)&u.y;
    float2 f0 = __half22float2(h0), f1 = __half22float2(h1);
    return make_float4(f0.x, f0.y, f1.x, f1.y);
}

// ---------------- dtype probe ----------------
__global__ void k_detect(const int* __restrict__ ei32) {
    int lane = threadIdx.x;
    int nz = 0;
#pragma unroll
    for (int i = 0; i < 2; i++) {
        int w = ei32[2 * (lane + 32 * i) + 1];
        nz |= (w != 0);
    }
    unsigned any = __ballot_sync(0xffffffffu, nz);
    if (lane == 0) g_is64 = (any == 0u) ? 1 : 0;
}

// ---------------- input fp32 -> fp16 ----------------
__global__ void k_xprep(const float* __restrict__ x) {
    int i = blockIdx.x * blockDim.x + threadIdx.x;   // over NN*DD/4
    if (i < NN * DD / 4) {
        float4 v = ((const float4*)x)[i];
        ((__half2*)g_x16)[2 * i]     = __floats2half2_rn(v.x, v.y);
        ((__half2*)g_x16)[2 * i + 1] = __floats2half2_rn(v.z, v.w);
    }
}

// ---------------- CSR build ----------------
__global__ void k_zero() {
    int i = blockIdx.x * blockDim.x + threadIdx.x;
    if (i < NN) g_deg[i] = 0;
}
__global__ void k_hist(const int* __restrict__ ei32) {
    int e = blockIdx.x * blockDim.x + threadIdx.x;
    if (e < NE) {
        int is64 = g_is64;
        unsigned d = is64 ? (unsigned)ei32[2 * (NE + e)] : (unsigned)ei32[NE + e];
        if (d < NN) atomicAdd(&g_deg[d], 1);
    }
}
__global__ void k_scan1() {
    __shared__ int ws[32];
    int i = blockIdx.x * SCAN_BLK + threadIdx.x;
    int v = (i < NN) ? g_deg[i] : 0;
    int s = v;
#pragma unroll
    for (int o = 16; o; o >>= 1) s += __shfl_xor_sync(0xffffffffu, s, o);
    if ((threadIdx.x & 31) == 0) ws[threadIdx.x >> 5] = s;
    __syncthreads();
    if (threadIdx.x < 32) {
        int t = ws[threadIdx.x];
#pragma unroll
        for (int o = 16; o; o >>= 1) t += __shfl_xor_sync(0xffffffffu, t, o);
        if (threadIdx.x == 0) g_bsum[blockIdx.x] = t;
    }
}
__global__ void k_scan2() {
    __shared__ int warp_incl[4];
    int t = threadIdx.x;
    int v = (t < NSB) ? g_bsum[t] : 0;
    int incl = v;
#pragma unroll
    for (int o = 1; o < 32; o <<= 1) {
        int u = __shfl_up_sync(0xffffffffu, incl, o);
        if ((t & 31) >= o) incl += u;
    }
    if ((t & 31) == 31) warp_incl[t >> 5] = incl;
    __syncthreads();
    int base = 0;
#pragma unroll
    for (int w = 0; w < 4; w++)
        if ((t >> 5) > w) base += warp_incl[w];
    incl += base;
    if (t < NSB) g_bpre[t] = incl - v;
    if (t == NSB - 1) g_off[NN] = incl;
}
__global__ void k_scan3() {
    __shared__ int wsum[32];
    int t = threadIdx.x;
    int i = blockIdx.x * SCAN_BLK + t;
    int v = (i < NN) ? g_deg[i] : 0;
    int lane = t & 31, wrp = t >> 5;
    int incl = v;
#pragma unroll
    for (int o = 1; o < 32; o <<= 1) {
        int u = __shfl_up_sync(0xffffffffu, incl, o);
        if (lane >= o) incl += u;
    }
    if (lane == 31) wsum[wrp] = incl;
    __syncthreads();
    if (wrp == 0) {
        int w = wsum[lane];
        int wincl = w;
#pragma unroll
        for (int o = 1; o < 32; o <<= 1) {
            int u = __shfl_up_sync(0xffffffffu, wincl, o);
            if (lane >= o) wincl += u;
        }
        wsum[lane] = wincl - w;
    }
    __syncthreads();
    if (i < NN) {
        int off = g_bpre[blockIdx.x] + wsum[wrp] + incl - v;
        g_off[i] = off;
        g_cur[i] = off;
    }
}
__global__ void k_scatter(const int* __restrict__ ei32) {
    int e = blockIdx.x * blockDim.x + threadIdx.x;
    if (e < NE) {
        int is64 = g_is64;
        unsigned d    = is64 ? (unsigned)ei32[2 * (NE + e)] : (unsigned)ei32[NE + e];
        unsigned srcv = is64 ? (unsigned)ei32[2 * e]        : (unsigned)ei32[e];
        if (d < NN && srcv < NN) {
            int pos = atomicAdd(&g_cur[d], 1);
            g_srcs[pos] = (int)srcv;
        }
    }
}

// ---------------- weight prep ----------------
__global__ void k_wprep(const float* __restrict__ w0, const float* __restrict__ w1,
                        const float* __restrict__ w2, const float* __restrict__ w3,
                        const float* __restrict__ w4, const float* __restrict__ w5) {
    int idx = blockIdx.x * blockDim.x + threadIdx.x;   // 6*128*128
    if (idx >= 6 * 128 * 128) return;
    int mat = idx >> 14;
    int k = (idx >> 7) & 127;
    int n = idx & 127;
    const float* W = (mat == 0) ? w0 : (mat == 1) ? w1 : (mat == 2) ? w2
                   : (mat == 3) ? w3 : (mat == 4) ? w4 : w5;
    float v = W[k * 128 + n];
    __nv_bfloat16 hi = __float2bfloat16(v);
    __nv_bfloat16 lo = __float2bfloat16(v - __bfloat162float(hi));
    __nv_bfloat16* dst = g_wb + (size_t)mat * 128 * 256 + (size_t)n * 256;
    dst[k] = hi;
    dst[128 + k] = lo;
}

// ---------------- aggregation: fp16 gather, fp32 accumulate, fp16 out ----------------
__global__ void k_agg(int layer) {
    int gw = (blockIdx.x * blockDim.x + threadIdx.x) >> 5;
    if (gw >= NN) return;
    int lane = threadIdx.x & 31;
    const __half* xin = (layer == 0) ? g_x16 : (g_xs16 + (size_t)(layer - 1) * NN * DD);
    const uint2* x2 = (const uint2*)xin;   // 4 halves per lane, 32 lanes = 256B row

    float4 acc = h4tof4(x2[(size_t)gw * 32 + lane]);
    int j = g_off[gw];
    int end = g_off[gw + 1];
    for (; j + 3 < end; j += 4) {
        int s0 = g_srcs[j], s1 = g_srcs[j + 1], s2 = g_srcs[j + 2], s3 = g_srcs[j + 3];
        uint2 ua = __ldg(&x2[(size_t)s0 * 32 + lane]);
        uint2 ub = __ldg(&x2[(size_t)s1 * 32 + lane]);
        uint2 uc = __ldg(&x2[(size_t)s2 * 32 + lane]);
        uint2 ud = __ldg(&x2[(size_t)s3 * 32 + lane]);
        float4 a = h4tof4(ua), b = h4tof4(ub), c = h4tof4(uc), d = h4tof4(ud);
        acc.x += (a.x + b.x) + (c.x + d.x);
        acc.y += (a.y + b.y) + (c.y + d.y);
        acc.z += (a.z + b.z) + (c.z + d.z);
        acc.w += (a.w + b.w) + (c.w + d.w);
    }
    for (; j < end; j++) {
        float4 a = h4tof4(__ldg(&x2[(size_t)g_srcs[j] * 32 + lane]));
        acc.x += a.x; acc.y += a.y; acc.z += a.z; acc.w += a.w;
    }
    uint2 o;
    *(__half2*)&o.x = __floats2half2_rn(acc.x, acc.y);
    *(__half2*)&o.y = __floats2half2_rn(acc.z, acc.w);
    ((uint2*)g_agg16)[(size_t)gw * 32 + lane] = o;
}

// ---------------- persistent mma.sync bf16 MLP (+ fused readout on layer 2) ----------------
// smem: A @0 (64KB), W1 @65536 (64KB), W2 @131072 (64KB)
#define SW1_OFF 65536u
#define SW2_OFF 131072u
#define SMEM_MLP 196608

__global__ __launch_bounds__(256)
void k_mlp(const float* __restrict__ b1, const float* __restrict__ b2,
           const float* __restrict__ Wm, const float* __restrict__ bm,
           float* __restrict__ final_out, int layer)
{
    extern __shared__ char smem[];
    const uint32_t sa = smem_u32(smem);
    const int tid = threadIdx.x, wid = tid >> 5, lane = tid & 31;
    const int wm = wid & 3, wn = wid >> 2;
    const int m0w = wm * 32;            // warp's 32 rows
    const int ncol0 = wn * 64;          // warp's 64 cols
    const int lr = lane & 7, grp = lane >> 3;
    const __nv_bfloat16* wb1 = g_wb + (size_t)(layer * 2)     * 128 * 256;
    const __nv_bfloat16* wb2 = g_wb + (size_t)(layer * 2 + 1) * 128 * 256;

    // ---- W1/W2 into swizzled smem (once per CTA) ----
    {
        int kb = lane * 16;
#pragma unroll 4
        for (int it = 0; it < 16; it++) {
            int n = wid + it * 8;
            uint4 r1 = ((const uint4*)(wb1 + (size_t)n * 256))[lane];
            uint4 r2 = ((const uint4*)(wb2 + (size_t)n * 256))[lane];
            uint32_t o = sws(n, kb);
            *(uint4*)(smem + SW1_OFF + o) = r1;
            *(uint4*)(smem + SW2_OFF + o) = r2;
        }
    }

    const int arow = lr + ((grp & 1) << 3);
    const int akadd = (grp & 2) ? 16 : 0;
    const int brow = lr + ((grp & 2) << 2);
    const int bkadd = (grp & 1) ? 16 : 0;
    const uint32_t lxor = (uint32_t)(lr << 4);
    uint32_t abase[2], bbase[4];
#pragma unroll
    for (int i = 0; i < 2; i++) abase[i] = sa + (uint32_t)((m0w + 16 * i + arow) * 512);
#pragma unroll
    for (int j = 0; j < 4; j++) bbase[j] = (uint32_t)((ncol0 + 16 * j + brow) * 512);

    float c[2][8][4];

    for (int tile = blockIdx.x; tile < NTILES; tile += gridDim.x) {
        const int base = tile * 128;
        __syncthreads();   // W ready / A+P free from previous tile

        // ---- build A (split hi/lo) from fp16 g_agg16 ----
        {
            const uint2* in2 = (const uint2*)g_agg16;
            int kb = lane * 8;
#pragma unroll 4
            for (int it = 0; it < 16; it++) {
                int m = wid + it * 8;
                int node = base + m;
                float4 v = make_float4(0.f, 0.f, 0.f, 0.f);
                if (node < NN) v = h4tof4(in2[(size_t)node * 32 + lane]);
                float hx = __bfloat162float(__float2bfloat16(v.x));
                float hy = __bfloat162float(__float2bfloat16(v.y));
                float hz = __bfloat162float(__float2bfloat16(v.z));
                float hw = __bfloat162float(__float2bfloat16(v.w));
                uint2 hi = make_uint2(pack_bf16(v.x, v.y), pack_bf16(v.z, v.w));
                uint2 lo = make_uint2(pack_bf16(v.x - hx, v.y - hy), pack_bf16(v.z - hz, v.w - hw));
                *(uint2*)(smem + sws(m, kb))       = hi;
                *(uint2*)(smem + sws(m, 256 + kb)) = lo;
            }
        }
        __syncthreads();

#pragma unroll 1
        for (int g = 0; g < 2; g++) {
            const uint32_t woff = sa + (g == 0 ? SW1_OFF : SW2_OFF);
#pragma unroll
            for (int i = 0; i < 2; i++)
#pragma unroll
                for (int j = 0; j < 8; j++)
#pragma unroll
                    for (int q = 0; q < 4; q++) c[i][j][q] = 0.f;

#pragma unroll 1
            for (int t = 0; t < 3; t++) {
                const int akoff = (t == 2) ? 256 : 0;
                const int bkoff = (t == 1) ? 256 : 0;
#pragma unroll
                for (int ks = 0; ks < 8; ks++) {
                    const int kb = ks * 32;
                    uint32_t fa[2][4], fb[8][2];
#pragma unroll
                    for (int i = 0; i < 2; i++)
                        ldsm4(fa[i][0], fa[i][1], fa[i][2], fa[i][3],
                              abase[i] + (uint32_t)((kb + akoff + akadd) ^ lxor));
#pragma unroll
                    for (int jj = 0; jj < 4; jj++) {
                        uint32_t r0, r1, r2, r3;
                        ldsm4(r0, r1, r2, r3,
                              woff + bbase[jj] + (uint32_t)((kb + bkoff + bkadd) ^ lxor));
                        fb[2 * jj][0] = r0; fb[2 * jj][1] = r1;
                        fb[2 * jj + 1][0] = r2; fb[2 * jj + 1][1] = r3;
                    }
#pragma unroll
                    for (int i = 0; i < 2; i++)
#pragma unroll
                        for (int j = 0; j < 8; j++)
                            mma16816(c[i][j], fa[i], fb[j]);
                }
            }

            if (g == 0) {
                __syncthreads();
#pragma unroll
                for (int j = 0; j < 8; j++) {
                    int n = ncol0 + 8 * j + 2 * (lane & 3);
                    float bn0 = __ldg(&b1[n]), bn1 = __ldg(&b1[n + 1]);
#pragma unroll
                    for (int i = 0; i < 2; i++) {
                        int r0 = m0w + 16 * i + (lane >> 2);
                        float h0 = fmaxf(c[i][j][0] + bn0, 0.f);
                        float h1 = fmaxf(c[i][j][1] + bn1, 0.f);
                        float h2 = fmaxf(c[i][j][2] + bn0, 0.f);
                        float h3 = fmaxf(c[i][j][3] + bn1, 0.f);
                        float t0 = __bfloat162float(__float2bfloat16(h0));
                        float t1 = __bfloat162float(__float2bfloat16(h1));
                        float t2 = __bfloat162float(__float2bfloat16(h2));
                        float t3 = __bfloat162float(__float2bfloat16(h3));
                        *(uint32_t*)(smem + sws(r0, 2 * n))           = pack_bf16(h0, h1);
                        *(uint32_t*)(smem + sws(r0, 256 + 2 * n))     = pack_bf16(h0 - t0, h1 - t1);
                        *(uint32_t*)(smem + sws(r0 + 8, 2 * n))       = pack_bf16(h2, h3);
                        *(uint32_t*)(smem + sws(r0 + 8, 256 + 2 * n)) = pack_bf16(h2 - t2, h3 - t3);
                    }
                }
                __syncthreads();
            }
        }

        if (layer < 2) {
            // ---- epilogue: bias + relu, write fp16 g_xs16[layer] ----
            __half* outp = g_xs16 + (size_t)layer * NN * DD;
#pragma unroll
            for (int j = 0; j < 8; j++) {
                int n = ncol0 + 8 * j + 2 * (lane & 3);
                float bn0 = __ldg(&b2[n]), bn1 = __ldg(&b2[n + 1]);
#pragma unroll
                for (int i = 0; i < 2; i++) {
                    int r0 = base + m0w + 16 * i + (lane >> 2);
                    float o0 = fmaxf(c[i][j][0] + bn0, 0.f);
                    float o1 = fmaxf(c[i][j][1] + bn1, 0.f);
                    float o2 = fmaxf(c[i][j][2] + bn0, 0.f);
                    float o3 = fmaxf(c[i][j][3] + bn1, 0.f);
                    if (r0 < NN)
                        *(__half2*)(outp + (size_t)r0 * DD + n) = __floats2half2_rn(o0, o1);
                    if (r0 + 8 < NN)
                        *(__half2*)(outp + (size_t)(r0 + 8) * DD + n) = __floats2half2_rn(o2, o3);
                }
            }
        } else {
            // ---- fused readout: z = x1.Wm1 + x2.Wm2 + x3.Wm3 + bm; sigmoid ----
            // 1) per-thread partial over its 16 cols of x3 (= c + b2, no relu)
            float part[2][2] = {{0.f, 0.f}, {0.f, 0.f}};   // [i][s]: rows m0w+16i+8s+(lane>>2)
#pragma unroll
            for (int j = 0; j < 8; j++) {
                int n = ncol0 + 8 * j + 2 * (lane & 3);
                float bn0 = __ldg(&b2[n]), bn1 = __ldg(&b2[n + 1]);
                float w0 = __ldg(&Wm[256 + n]), w1 = __ldg(&Wm[256 + n + 1]);
#pragma unroll
                for (int i = 0; i < 2; i++) {
                    part[i][0] += (c[i][j][0] + bn0) * w0 + (c[i][j][1] + bn1) * w1;
                    part[i][1] += (c[i][j][2] + bn0) * w0 + (c[i][j][3] + bn1) * w1;
                }
            }
            __syncthreads();   // A region free (all GEMM2 reads done)
            float* P = (float*)smem;   // [128][9]
            int cslot = wn * 4 + (lane & 3);
#pragma unroll
            for (int i = 0; i < 2; i++)
#pragma unroll
                for (int s = 0; s < 2; s++) {
                    int row = m0w + 16 * i + 8 * s + (lane >> 2);
                    P[row * 9 + cslot] = part[i][s];
                }
            __syncthreads();
            // 2) warp-per-16-rows: x1/x2 dot + partial sum + sigmoid
            float4 wv1 = __ldg(&((const float4*)Wm)[lane]);
            float4 wv2 = __ldg(&((const float4*)(Wm + 128))[lane]);
            float bmv = __ldg(bm);
            const uint2* x1 = (const uint2*)g_xs16;
            const uint2* x2 = (const uint2*)(g_xs16 + (size_t)NN * DD);
            for (int r = wid * 16; r < wid * 16 + 16; r++) {
                int node = base + r;
                if (node >= NN) break;
                float4 v1 = h4tof4(__ldg(&x1[(size_t)node * 32 + lane]));
                float4 v2 = h4tof4(__ldg(&x2[(size_t)node * 32 + lane]));
                float a = v1.x * wv1.x + v1.y * wv1.y + v1.z * wv1.z + v1.w * wv1.w
                        + v2.x * wv2.x + v2.y * wv2.y + v2.z * wv2.z + v2.w * wv2.w;
                if (lane < 8) a += P[r * 9 + lane];
#pragma unroll
                for (int o = 16; o; o >>= 1) a += __shfl_xor_sync(0xffffffffu, a, o);
                if (lane == 0) final_out[node] = 1.0f / (1.0f + expf(-(a + bmv)));
            }
        }
    }
}

// ---------------- launch ----------------
extern "C" void kernel_launch(void* const* d_in, const int* in_sizes, int n_in,
                              void* d_out, int out_size) {
    const float* x  = (const float*)d_in[0];
    const int*   ei = (const int*)d_in[1];
    const float* W1[3] = {(const float*)d_in[3],  (const float*)d_in[7],  (const float*)d_in[11]};
    const float* b1[3] = {(const float*)d_in[4],  (const float*)d_in[8],  (const float*)d_in[12]};
    const float* W2[3] = {(const float*)d_in[5],  (const float*)d_in[9],  (const float*)d_in[13]};
    const float* b2[3] = {(const float*)d_in[6],  (const float*)d_in[10], (const float*)d_in[14]};
    const float* Wm = (const float*)d_in[15];
    const float* bm = (const float*)d_in[16];
    float* out = (float*)d_out;

    cudaFuncSetAttribute(k_mlp, cudaFuncAttributeMaxDynamicSharedMemorySize, SMEM_MLP);

    // CSR build + prep (deterministic every launch)
    k_detect<<<1, 32>>>(ei);
    k_zero<<<(NN + 255) / 256, 256>>>();
    k_hist<<<(NE + 255) / 256, 256>>>(ei);
    k_scan1<<<NSB, SCAN_BLK>>>();
    k_scan2<<<1, 128>>>();
    k_scan3<<<NSB, SCAN_BLK>>>();
    k_scatter<<<(NE + 255) / 256, 256>>>(ei);
    k_wprep<<<(6 * 128 * 128 + 255) / 256, 256>>>(W1[0], W2[0], W1[1], W2[1], W1[2], W2[2]);
    k_xprep<<<(NN * DD / 4 + 255) / 256, 256>>>(x);

    const int AGG_BLOCKS = (NN * 32 + 255) / 256;   // 12500

    for (int l = 0; l < 3; l++) {
        k_agg<<<AGG_BLOCKS, 256>>>(l);
        k_mlp<<<MLP_GRID, 256, SMEM_MLP>>>(b1[l], b2[l], Wm, bm, out, l);
    }
}

// round 13
// speedup vs baseline: 1.0170x; 1.0170x over previous
#include <cuda_runtime.h>
#include <cuda_bf16.h>
#include <cuda_fp16.h>
#include <stdint.h>
#include <math.h>

#define NN 100000
#define NE 1600000
#define DD 128
#define SCAN_BLK 1024
#define NSB ((NN + SCAN_BLK - 1) / SCAN_BLK)   // 98 scan blocks

// ---------------- scratch (device globals; no allocation) ----------------
__device__ alignas(16) __half g_agg16[(size_t)NN * DD];       // 25.6 MB (fp16 MLP input)
__device__ alignas(16) __half g_x16[(size_t)NN * DD];         // 25.6 MB (fp16 input copy)
__device__ alignas(16) __half g_xs16[(size_t)3 * NN * DD];    // 76.8 MB (fp16 layer outputs)
__device__ alignas(16) __nv_bfloat16 g_wb[6 * 128 * 256];     // split weights [mat][n][k: hi|lo]
__device__ alignas(16) int   g_deg[NN];
__device__ alignas(16) int   g_cur[NN];
__device__ alignas(16) int   g_srcs[NE];
__device__ alignas(16) int   g_off[NN + 1];
__device__ alignas(16) int   g_bsum[NSB];
__device__ alignas(16) int   g_bpre[NSB];
__device__ int g_is64;

__device__ __forceinline__ uint32_t smem_u32(const void* p) {
    uint32_t a;
    asm("{ .reg .u64 t; cvta.to.shared.u64 t, %1; cvt.u32.u64 %0, t; }" : "=r"(a) : "l"(p));
    return a;
}
__device__ __forceinline__ uint32_t pack_bf16(float a, float b) {
    __nv_bfloat16 ha = __float2bfloat16(a), hb = __float2bfloat16(b);
    return (uint32_t)__bfloat16_as_ushort(ha) | ((uint32_t)__bfloat16_as_ushort(hb) << 16);
}
__device__ __forceinline__ void ldsm4(uint32_t& r0, uint32_t& r1, uint32_t& r2, uint32_t& r3, uint32_t addr) {
    asm volatile("ldmatrix.sync.aligned.m8n8.x4.shared.b16 {%0,%1,%2,%3}, [%4];"
                 : "=r"(r0), "=r"(r1), "=r"(r2), "=r"(r3) : "r"(addr));
}
__device__ __forceinline__ void mma16816(float* c, const uint32_t* a, const uint32_t* b) {
    asm volatile("mma.sync.aligned.m16n8k16.row.col.f32.bf16.bf16.f32 "
                 "{%0,%1,%2,%3}, {%4,%5,%6,%7}, {%8,%9}, {%0,%1,%2,%3};"
                 : "+f"(c[0]), "+f"(c[1]), "+f"(c[2]), "+f"(c[3])
                 : "r"(a[0]), "r"(a[1]), "r"(a[2]), "r"(a[3]), "r"(b[0]), "r"(b[1]));
}
// swizzled smem byte offset within a 512B bf16 row (k: hi bytes 0-255, lo 256-511)
__device__ __forceinline__ uint32_t sws(int row, int kb) {
    return (uint32_t)(row * 512 + (kb ^ ((row & 7) << 4)));
}
// unpack 4 packed halves (uint2) -> float4
__device__ __forceinline__ float4 h4tof4(uint2 u) {
    __half2 h0 = *(__half2*)&u.x, h1 = *(__half2*)&u.y;
    float2 f0 = __half22float2(h0), f1 = __half22float2(h1);
    return make_float4(f0.x, f0.y, f1.x, f1.y);
}

// ---------------- dtype probe ----------------
__global__ void k_detect(const int* __restrict__ ei32) {
    int lane = threadIdx.x;
    int nz = 0;
#pragma unroll
    for (int i = 0; i < 2; i++) {
        int w = ei32[2 * (lane + 32 * i) + 1];
        nz |= (w != 0);
    }
    unsigned any = __ballot_sync(0xffffffffu, nz);
    if (lane == 0) g_is64 = (any == 0u) ? 1 : 0;
}

// ---------------- input fp32 -> fp16 ----------------
__global__ void k_xprep(const float* __restrict__ x) {
    int i = blockIdx.x * blockDim.x + threadIdx.x;   // over NN*DD/4
    if (i < NN * DD / 4) {
        float4 v = ((const float4*)x)[i];
        ((__half2*)g_x16)[2 * i]     = __floats2half2_rn(v.x, v.y);
        ((__half2*)g_x16)[2 * i + 1] = __floats2half2_rn(v.z, v.w);
    }
}

// ---------------- CSR build ----------------
__global__ void k_zero() {
    int i = blockIdx.x * blockDim.x + threadIdx.x;
    if (i < NN) g_deg[i] = 0;
}
__global__ void k_hist(const int* __restrict__ ei32) {
    int e = blockIdx.x * blockDim.x + threadIdx.x;
    if (e < NE) {
        int is64 = g_is64;
        unsigned d = is64 ? (unsigned)ei32[2 * (NE + e)] : (unsigned)ei32[NE + e];
        if (d < NN) atomicAdd(&g_deg[d], 1);
    }
}
__global__ void k_scan1() {
    __shared__ int ws[32];
    int i = blockIdx.x * SCAN_BLK + threadIdx.x;
    int v = (i < NN) ? g_deg[i] : 0;
    int s = v;
#pragma unroll
    for (int o = 16; o; o >>= 1) s += __shfl_xor_sync(0xffffffffu, s, o);
    if ((threadIdx.x & 31) == 0) ws[threadIdx.x >> 5] = s;
    __syncthreads();
    if (threadIdx.x < 32) {
        int t = ws[threadIdx.x];
#pragma unroll
        for (int o = 16; o; o >>= 1) t += __shfl_xor_sync(0xffffffffu, t, o);
        if (threadIdx.x == 0) g_bsum[blockIdx.x] = t;
    }
}
__global__ void k_scan2() {
    __shared__ int warp_incl[4];
    int t = threadIdx.x;
    int v = (t < NSB) ? g_bsum[t] : 0;
    int incl = v;
#pragma unroll
    for (int o = 1; o < 32; o <<= 1) {
        int u = __shfl_up_sync(0xffffffffu, incl, o);
        if ((t & 31) >= o) incl += u;
    }
    if ((t & 31) == 31) warp_incl[t >> 5] = incl;
    __syncthreads();
    int base = 0;
#pragma unroll
    for (int w = 0; w < 4; w++)
        if ((t >> 5) > w) base += warp_incl[w];
    incl += base;
    if (t < NSB) g_bpre[t] = incl - v;
    if (t == NSB - 1) g_off[NN] = incl;
}
__global__ void k_scan3() {
    __shared__ int wsum[32];
    int t = threadIdx.x;
    int i = blockIdx.x * SCAN_BLK + t;
    int v = (i < NN) ? g_deg[i] : 0;
    int lane = t & 31, wrp = t >> 5;
    int incl = v;
#pragma unroll
    for (int o = 1; o < 32; o <<= 1) {
        int u = __shfl_up_sync(0xffffffffu, incl, o);
        if (lane >= o) incl += u;
    }
    if (lane == 31) wsum[wrp] = incl;
    __syncthreads();
    if (wrp == 0) {
        int w = wsum[lane];
        int wincl = w;
#pragma unroll
        for (int o = 1; o < 32; o <<= 1) {
            int u = __shfl_up_sync(0xffffffffu, wincl, o);
            if (lane >= o) wincl += u;
        }
        wsum[lane] = wincl - w;
    }
    __syncthreads();
    if (i < NN) {
        int off = g_bpre[blockIdx.x] + wsum[wrp] + incl - v;
        g_off[i] = off;
        g_cur[i] = off;
    }
}
__global__ void k_scatter(const int* __restrict__ ei32) {
    int e = blockIdx.x * blockDim.x + threadIdx.x;
    if (e < NE) {
        int is64 = g_is64;
        unsigned d    = is64 ? (unsigned)ei32[2 * (NE + e)] : (unsigned)ei32[NE + e];
        unsigned srcv = is64 ? (unsigned)ei32[2 * e]        : (unsigned)ei32[e];
        if (d < NN && srcv < NN) {
            int pos = atomicAdd(&g_cur[d], 1);
            g_srcs[pos] = (int)srcv;
        }
    }
}

// ---------------- weight prep ----------------
__global__ void k_wprep(const float* __restrict__ w0, const float* __restrict__ w1,
                        const float* __restrict__ w2, const float* __restrict__ w3,
                        const float* __restrict__ w4, const float* __restrict__ w5) {
    int idx = blockIdx.x * blockDim.x + threadIdx.x;   // 6*128*128
    if (idx >= 6 * 128 * 128) return;
    int mat = idx >> 14;
    int k = (idx >> 7) & 127;
    int n = idx & 127;
    const float* W = (mat == 0) ? w0 : (mat == 1) ? w1 : (mat == 2) ? w2
                   : (mat == 3) ? w3 : (mat == 4) ? w4 : w5;
    float v = W[k * 128 + n];
    __nv_bfloat16 hi = __float2bfloat16(v);
    __nv_bfloat16 lo = __float2bfloat16(v - __bfloat162float(hi));
    __nv_bfloat16* dst = g_wb + (size_t)mat * 128 * 256 + (size_t)n * 256;
    dst[k] = hi;
    dst[128 + k] = lo;
}

// ---------------- aggregation: fp16 gather, fp32 accumulate, fp16 out ----------------
__global__ void k_agg(int layer) {
    int gw = (blockIdx.x * blockDim.x + threadIdx.x) >> 5;
    if (gw >= NN) return;
    int lane = threadIdx.x & 31;
    const __half* xin = (layer == 0) ? g_x16 : (g_xs16 + (size_t)(layer - 1) * NN * DD);
    const uint2* x2 = (const uint2*)xin;   // 4 halves per lane, 32 lanes = 256B row

    float4 acc = h4tof4(x2[(size_t)gw * 32 + lane]);
    int j = g_off[gw];
    int end = g_off[gw + 1];
    for (; j + 3 < end; j += 4) {
        int s0 = g_srcs[j], s1 = g_srcs[j + 1], s2 = g_srcs[j + 2], s3 = g_srcs[j + 3];
        uint2 ua = __ldg(&x2[(size_t)s0 * 32 + lane]);
        uint2 ub = __ldg(&x2[(size_t)s1 * 32 + lane]);
        uint2 uc = __ldg(&x2[(size_t)s2 * 32 + lane]);
        uint2 ud = __ldg(&x2[(size_t)s3 * 32 + lane]);
        float4 a = h4tof4(ua), b = h4tof4(ub), c = h4tof4(uc), d = h4tof4(ud);
        acc.x += (a.x + b.x) + (c.x + d.x);
        acc.y += (a.y + b.y) + (c.y + d.y);
        acc.z += (a.z + b.z) + (c.z + d.z);
        acc.w += (a.w + b.w) + (c.w + d.w);
    }
    for (; j < end; j++) {
        float4 a = h4tof4(__ldg(&x2[(size_t)g_srcs[j] * 32 + lane]));
        acc.x += a.x; acc.y += a.y; acc.z += a.z; acc.w += a.w;
    }
    uint2 o;
    *(__half2*)&o.x = __floats2half2_rn(acc.x, acc.y);
    *(__half2*)&o.y = __floats2half2_rn(acc.z, acc.w);
    ((uint2*)g_agg16)[(size_t)gw * 32 + lane] = o;
}

// ---------------- mma.sync bf16 MLP: 128x128 tile per CTA ----------------
// smem: A @0 (128 rows x 512B = 64KB), W1 @65536 (64KB), W2 @131072 (64KB)
#define SW1_OFF 65536u
#define SW2_OFF 131072u
#define SMEM_MLP 196608

__global__ __launch_bounds__(256)
void k_mlp(const float* __restrict__ b1, const float* __restrict__ b2, int layer)
{
    extern __shared__ char smem[];
    const uint32_t sa = smem_u32(smem);
    const int tid = threadIdx.x, wid = tid >> 5, lane = tid & 31;
    const int base = blockIdx.x * 128;
    const int wm = wid & 3, wn = wid >> 2;
    const int m0w = wm * 32;            // warp's 32 rows
    const int ncol0 = wn * 64;          // warp's 64 cols
    const int lr = lane & 7, grp = lane >> 3;
    const __nv_bfloat16* wb1 = g_wb + (size_t)(layer * 2)     * 128 * 256;
    const __nv_bfloat16* wb2 = g_wb + (size_t)(layer * 2 + 1) * 128 * 256;

    // ---- build A (split hi/lo) from fp16 g_agg16 ----
    {
        const uint2* in2 = (const uint2*)g_agg16;
        int kb = lane * 8;
#pragma unroll 4
        for (int it = 0; it < 16; it++) {
            int m = wid + it * 8;
            int node = base + m;
            float4 v = make_float4(0.f, 0.f, 0.f, 0.f);
            if (node < NN) v = h4tof4(in2[(size_t)node * 32 + lane]);
            float hx = __bfloat162float(__float2bfloat16(v.x));
            float hy = __bfloat162float(__float2bfloat16(v.y));
            float hz = __bfloat162float(__float2bfloat16(v.z));
            float hw = __bfloat162float(__float2bfloat16(v.w));
            uint2 hi = make_uint2(pack_bf16(v.x, v.y), pack_bf16(v.z, v.w));
            uint2 lo = make_uint2(pack_bf16(v.x - hx, v.y - hy), pack_bf16(v.z - hz, v.w - hw));
            *(uint2*)(smem + sws(m, kb))       = hi;
            *(uint2*)(smem + sws(m, 256 + kb)) = lo;
        }
    }
    // ---- load W1/W2 into swizzled smem ----
    {
        int kb = lane * 16;
#pragma unroll 4
        for (int it = 0; it < 16; it++) {
            int n = wid + it * 8;
            uint4 r1 = ((const uint4*)(wb1 + (size_t)n * 256))[lane];
            uint4 r2 = ((const uint4*)(wb2 + (size_t)n * 256))[lane];
            uint32_t o = sws(n, kb);
            *(uint4*)(smem + SW1_OFF + o) = r1;
            *(uint4*)(smem + SW2_OFF + o) = r2;
        }
    }
    __syncthreads();

    const int arow = lr + ((grp & 1) << 3);
    const int akadd = (grp & 2) ? 16 : 0;
    const int brow = lr + ((grp & 2) << 2);
    const int bkadd = (grp & 1) ? 16 : 0;
    const uint32_t lxor = (uint32_t)(lr << 4);
    uint32_t abase[2], bbase[4];
#pragma unroll
    for (int i = 0; i < 2; i++) abase[i] = sa + (uint32_t)((m0w + 16 * i + arow) * 512);
#pragma unroll
    for (int j = 0; j < 4; j++) bbase[j] = (uint32_t)((ncol0 + 16 * j + brow) * 512);

    float c[2][8][4];

#pragma unroll 1
    for (int g = 0; g < 2; g++) {
        const uint32_t woff = sa + (g == 0 ? SW1_OFF : SW2_OFF);
#pragma unroll
        for (int i = 0; i < 2; i++)
#pragma unroll
            for (int j = 0; j < 8; j++)
#pragma unroll
                for (int q = 0; q < 4; q++) c[i][j][q] = 0.f;

#pragma unroll 1
        for (int t = 0; t < 3; t++) {
            const int akoff = (t == 2) ? 256 : 0;
            const int bkoff = (t == 1) ? 256 : 0;
#pragma unroll
            for (int ks = 0; ks < 8; ks++) {
                const int kb = ks * 32;
                uint32_t fa[2][4], fb[8][2];
#pragma unroll
                for (int i = 0; i < 2; i++)
                    ldsm4(fa[i][0], fa[i][1], fa[i][2], fa[i][3],
                          abase[i] + (uint32_t)((kb + akoff + akadd) ^ lxor));
#pragma unroll
                for (int jj = 0; jj < 4; jj++) {
                    uint32_t r0, r1, r2, r3;
                    ldsm4(r0, r1, r2, r3,
                          woff + bbase[jj] + (uint32_t)((kb + bkoff + bkadd) ^ lxor));
                    fb[2 * jj][0] = r0; fb[2 * jj][1] = r1;
                    fb[2 * jj + 1][0] = r2; fb[2 * jj + 1][1] = r3;
                }
#pragma unroll
                for (int i = 0; i < 2; i++)
#pragma unroll
                    for (int j = 0; j < 8; j++)
                        mma16816(c[i][j], fa[i], fb[j]);
            }
        }

        if (g == 0) {
            __syncthreads();
#pragma unroll
            for (int j = 0; j < 8; j++) {
                int n = ncol0 + 8 * j + 2 * (lane & 3);
                float bn0 = __ldg(&b1[n]), bn1 = __ldg(&b1[n + 1]);
#pragma unroll
                for (int i = 0; i < 2; i++) {
                    int r0 = m0w + 16 * i + (lane >> 2);
                    float h0 = fmaxf(c[i][j][0] + bn0, 0.f);
                    float h1 = fmaxf(c[i][j][1] + bn1, 0.f);
                    float h2 = fmaxf(c[i][j][2] + bn0, 0.f);
                    float h3 = fmaxf(c[i][j][3] + bn1, 0.f);
                    float t0 = __bfloat162float(__float2bfloat16(h0));
                    float t1 = __bfloat162float(__float2bfloat16(h1));
                    float t2 = __bfloat162float(__float2bfloat16(h2));
                    float t3 = __bfloat162float(__float2bfloat16(h3));
                    *(uint32_t*)(smem + sws(r0, 2 * n))           = pack_bf16(h0, h1);
                    *(uint32_t*)(smem + sws(r0, 256 + 2 * n))     = pack_bf16(h0 - t0, h1 - t1);
                    *(uint32_t*)(smem + sws(r0 + 8, 2 * n))       = pack_bf16(h2, h3);
                    *(uint32_t*)(smem + sws(r0 + 8, 256 + 2 * n)) = pack_bf16(h2 - t2, h3 - t3);
                }
            }
            __syncthreads();
        }
    }

    // ---- epilogue 2: bias (+relu), write fp16 g_xs16[layer] ----
    {
        const int relu_out = (layer < 2);
        __half* outp = g_xs16 + (size_t)layer * NN * DD;
#pragma unroll
        for (int j = 0; j < 8; j++) {
            int n = ncol0 + 8 * j + 2 * (lane & 3);
            float bn0 = __ldg(&b2[n]), bn1 = __ldg(&b2[n + 1]);
#pragma unroll
            for (int i = 0; i < 2; i++) {
                int r0 = base + m0w + 16 * i + (lane >> 2);
                float o0 = c[i][j][0] + bn0, o1 = c[i][j][1] + bn1;
                float o2 = c[i][j][2] + bn0, o3 = c[i][j][3] + bn1;
                if (relu_out) {
                    o0 = fmaxf(o0, 0.f); o1 = fmaxf(o1, 0.f);
                    o2 = fmaxf(o2, 0.f); o3 = fmaxf(o3, 0.f);
                }
                if (r0 < NN)
                    *(__half2*)(outp + (size_t)r0 * DD + n) = __floats2half2_rn(o0, o1);
                if (r0 + 8 < NN)
                    *(__half2*)(outp + (size_t)(r0 + 8) * DD + n) = __floats2half2_rn(o2, o3);
            }
        }
    }
}

// ---------------- readout: fp16 activations ----------------
__global__ void k_readout(const float* __restrict__ Wm, const float* __restrict__ bm,
                          float* __restrict__ out) {
    int gw = (blockIdx.x * blockDim.x + threadIdx.x) >> 5;
    if (gw >= NN) return;
    int lane = threadIdx.x & 31;
    float acc = 0.f;
#pragma unroll
    for (int l = 0; l < 3; l++) {
        const uint2* xs2 = (const uint2*)(g_xs16 + (size_t)l * NN * DD);
        float4 v = h4tof4(xs2[(size_t)gw * 32 + lane]);
        float4 w = __ldg(&((const float4*)(Wm + l * 128))[lane]);
        acc += v.x * w.x + v.y * w.y + v.z * w.z + v.w * w.w;
    }
#pragma unroll
    for (int o = 16; o; o >>= 1) acc += __shfl_xor_sync(0xffffffffu, acc, o);
    if (lane == 0) {
        float z = acc + __ldg(bm);
        out[gw] = 1.0f / (1.0f + expf(-z));
    }
}

// ---------------- launch ----------------
extern "C" void kernel_launch(void* const* d_in, const int* in_sizes, int n_in,
                              void* d_out, int out_size) {
    const float* x  = (const float*)d_in[0];
    const int*   ei = (const int*)d_in[1];
    const float* W1[3] = {(const float*)d_in[3],  (const float*)d_in[7],  (const float*)d_in[11]};
    const float* b1[3] = {(const float*)d_in[4],  (const float*)d_in[8],  (const float*)d_in[12]};
    const float* W2[3] = {(const float*)d_in[5],  (const float*)d_in[9],  (const float*)d_in[13]};
    const float* b2[3] = {(const float*)d_in[6],  (const float*)d_in[10], (const float*)d_in[14]};
    const float* Wm = (const float*)d_in[15];
    const float* bm = (const float*)d_in[16];
    float* out = (float*)d_out;

    cudaFuncSetAttribute(k_mlp, cudaFuncAttributeMaxDynamicSharedMemorySize, SMEM_MLP);

    // CSR build + prep (deterministic every launch)
    k_detect<<<1, 32>>>(ei);
    k_zero<<<(NN + 255) / 256, 256>>>();
    k_hist<<<(NE + 255) / 256, 256>>>(ei);
    k_scan1<<<NSB, SCAN_BLK>>>();
    k_scan2<<<1, 128>>>();
    k_scan3<<<NSB, SCAN_BLK>>>();
    k_scatter<<<(NE + 255) / 256, 256>>>(ei);
    k_wprep<<<(6 * 128 * 128 + 255) / 256, 256>>>(W1[0], W2[0], W1[1], W2[1], W1[2], W2[2]);
    k_xprep<<<(NN * DD / 4 + 255) / 256, 256>>>(x);

    const int AGG_BLOCKS = (NN * 32 + 255) / 256;   // 12500
    const int MLP_BLOCKS = (NN + 127) / 128;        // 782

    for (int l = 0; l < 3; l++) {
        k_agg<<<AGG_BLOCKS, 256>>>(l);
        k_mlp<<<MLP_BLOCKS, 256, SMEM_MLP>>>(b1[l], b2[l], l);
    }
    k_readout<<<AGG_BLOCKS, 256>>>(Wm, bm, out);
}

// round 14
// speedup vs baseline: 1.2232x; 1.2028x over previous
#include <cuda_runtime.h>
#include <cuda_bf16.h>
#include <cuda_fp16.h>
#include <stdint.h>
#include <math.h>

#define NN 100000
#define NE 1600000
#define DD 128
#define SCAN_BLK 1024
#define NSB ((NN + SCAN_BLK - 1) / SCAN_BLK)   // 98 scan blocks

// ---------------- scratch (device globals; no allocation) ----------------
__device__ alignas(16) __half g_agg16[(size_t)NN * DD];       // 25.6 MB (fp16 MLP input)
__device__ alignas(16) __half g_x16[(size_t)NN * DD];         // 25.6 MB (fp16 input copy)
__device__ alignas(16) __half g_xs16[(size_t)3 * NN * DD];    // 76.8 MB (fp16 layer outputs)
__device__ alignas(16) __half g_wb[6 * 128 * 256];            // fp16 split weights [mat][n][k: hi|lo]
__device__ alignas(16) int   g_deg[NN];
__device__ alignas(16) int   g_cur[NN];
__device__ alignas(16) int   g_srcs[NE];
__device__ alignas(16) int   g_off[NN + 1];
__device__ alignas(16) int   g_bsum[NSB];
__device__ alignas(16) int   g_bpre[NSB];
__device__ int g_is64;

__device__ __forceinline__ uint32_t smem_u32(const void* p) {
    uint32_t a;
    asm("{ .reg .u64 t; cvta.to.shared.u64 t, %1; cvt.u32.u64 %0, t; }" : "=r"(a) : "l"(p));
    return a;
}
__device__ __forceinline__ void ldsm4(uint32_t& r0, uint32_t& r1, uint32_t& r2, uint32_t& r3, uint32_t addr) {
    asm volatile("ldmatrix.sync.aligned.m8n8.x4.shared.b16 {%0,%1,%2,%3}, [%4];"
                 : "=r"(r0), "=r"(r1), "=r"(r2), "=r"(r3) : "r"(addr));
}
// f16 tensor-core MMA (sm_80+ baseline PTX)
__device__ __forceinline__ void mma16816(float* c, const uint32_t* a, const uint32_t* b) {
    asm volatile("mma.sync.aligned.m16n8k16.row.col.f32.f16.f16.f32 "
                 "{%0,%1,%2,%3}, {%4,%5,%6,%7}, {%8,%9}, {%0,%1,%2,%3};"
                 : "+f"(c[0]), "+f"(c[1]), "+f"(c[2]), "+f"(c[3])
                 : "r"(a[0]), "r"(a[1]), "r"(a[2]), "r"(a[3]), "r"(b[0]), "r"(b[1]));
}
// swizzled smem byte offset within a 512B row (W: k hi bytes 0-255, lo 256-511)
__device__ __forceinline__ uint32_t sws(int row, int kb) {
    return (uint32_t)(row * 512 + (kb ^ ((row & 7) << 4)));
}
// swizzled smem byte offset within a 256B fp16 row (A: 128 fp16)
__device__ __forceinline__ uint32_t swsA(int row, int kb) {
    return (uint32_t)(row * 256 + (kb ^ ((row & 7) << 4)));
}
// unpack 4 packed halves (uint2) -> float4
__device__ __forceinline__ float4 h4tof4(uint2 u) {
    __half2 h0 = *(__half2*)&u.x, h1 = *(__half2*)&u.y;
    float2 f0 = __half22float2(h0), f1 = __half22float2(h1);
    return make_float4(f0.x, f0.y, f1.x, f1.y);
}
__device__ __forceinline__ uint32_t packh2(float a, float b) {
    __half2 h = __floats2half2_rn(a, b);
    return *(uint32_t*)&h;
}

// ---------------- dtype probe ----------------
__global__ void k_detect(const int* __restrict__ ei32) {
    int lane = threadIdx.x;
    int nz = 0;
#pragma unroll
    for (int i = 0; i < 2; i++) {
        int w = ei32[2 * (lane + 32 * i) + 1];
        nz |= (w != 0);
    }
    unsigned any = __ballot_sync(0xffffffffu, nz);
    if (lane == 0) g_is64 = (any == 0u) ? 1 : 0;
}

// ---------------- input fp32 -> fp16 ----------------
__global__ void k_xprep(const float* __restrict__ x) {
    int i = blockIdx.x * blockDim.x + threadIdx.x;   // over NN*DD/4
    if (i < NN * DD / 4) {
        float4 v = ((const float4*)x)[i];
        ((__half2*)g_x16)[2 * i]     = __floats2half2_rn(v.x, v.y);
        ((__half2*)g_x16)[2 * i + 1] = __floats2half2_rn(v.z, v.w);
    }
}

// ---------------- CSR build ----------------
__global__ void k_zero() {
    int i = blockIdx.x * blockDim.x + threadIdx.x;
    if (i < NN) g_deg[i] = 0;
}
__global__ void k_hist(const int* __restrict__ ei32) {
    int e = blockIdx.x * blockDim.x + threadIdx.x;
    if (e < NE) {
        int is64 = g_is64;
        unsigned d = is64 ? (unsigned)ei32[2 * (NE + e)] : (unsigned)ei32[NE + e];
        if (d < NN) atomicAdd(&g_deg[d], 1);
    }
}
__global__ void k_scan1() {
    __shared__ int ws[32];
    int i = blockIdx.x * SCAN_BLK + threadIdx.x;
    int v = (i < NN) ? g_deg[i] : 0;
    int s = v;
#pragma unroll
    for (int o = 16; o; o >>= 1) s += __shfl_xor_sync(0xffffffffu, s, o);
    if ((threadIdx.x & 31) == 0) ws[threadIdx.x >> 5] = s;
    __syncthreads();
    if (threadIdx.x < 32) {
        int t = ws[threadIdx.x];
#pragma unroll
        for (int o = 16; o; o >>= 1) t += __shfl_xor_sync(0xffffffffu, t, o);
        if (threadIdx.x == 0) g_bsum[blockIdx.x] = t;
    }
}
__global__ void k_scan2() {
    __shared__ int warp_incl[4];
    int t = threadIdx.x;
    int v = (t < NSB) ? g_bsum[t] : 0;
    int incl = v;
#pragma unroll
    for (int o = 1; o < 32; o <<= 1) {
        int u = __shfl_up_sync(0xffffffffu, incl, o);
        if ((t & 31) >= o) incl += u;
    }
    if ((t & 31) == 31) warp_incl[t >> 5] = incl;
    __syncthreads();
    int base = 0;
#pragma unroll
    for (int w = 0; w < 4; w++)
        if ((t >> 5) > w) base += warp_incl[w];
    incl += base;
    if (t < NSB) g_bpre[t] = incl - v;
    if (t == NSB - 1) g_off[NN] = incl;
}
__global__ void k_scan3() {
    __shared__ int wsum[32];
    int t = threadIdx.x;
    int i = blockIdx.x * SCAN_BLK + t;
    int v = (i < NN) ? g_deg[i] : 0;
    int lane = t & 31, wrp = t >> 5;
    int incl = v;
#pragma unroll
    for (int o = 1; o < 32; o <<= 1) {
        int u = __shfl_up_sync(0xffffffffu, incl, o);
        if (lane >= o) incl += u;
    }
    if (lane == 31) wsum[wrp] = incl;
    __syncthreads();
    if (wrp == 0) {
        int w = wsum[lane];
        int wincl = w;
#pragma unroll
        for (int o = 1; o < 32; o <<= 1) {
            int u = __shfl_up_sync(0xffffffffu, wincl, o);
            if (lane >= o) wincl += u;
        }
        wsum[lane] = wincl - w;
    }
    __syncthreads();
    if (i < NN) {
        int off = g_bpre[blockIdx.x] + wsum[wrp] + incl - v;
        g_off[i] = off;
        g_cur[i] = off;
    }
}
__global__ void k_scatter(const int* __restrict__ ei32) {
    int e = blockIdx.x * blockDim.x + threadIdx.x;
    if (e < NE) {
        int is64 = g_is64;
        unsigned d    = is64 ? (unsigned)ei32[2 * (NE + e)] : (unsigned)ei32[NE + e];
        unsigned srcv = is64 ? (unsigned)ei32[2 * e]        : (unsigned)ei32[e];
        if (d < NN && srcv < NN) {
            int pos = atomicAdd(&g_cur[d], 1);
            g_srcs[pos] = (int)srcv;
        }
    }
}

// ---------------- weight prep: W[k][n] fp32 -> fp16 hi/lo transposed [n][hi(k)|lo(k)] ----------------
__global__ void k_wprep(const float* __restrict__ w0, const float* __restrict__ w1,
                        const float* __restrict__ w2, const float* __restrict__ w3,
                        const float* __restrict__ w4, const float* __restrict__ w5) {
    int idx = blockIdx.x * blockDim.x + threadIdx.x;   // 6*128*128
    if (idx >= 6 * 128 * 128) return;
    int mat = idx >> 14;
    int k = (idx >> 7) & 127;
    int n = idx & 127;
    const float* W = (mat == 0) ? w0 : (mat == 1) ? w1 : (mat == 2) ? w2
                   : (mat == 3) ? w3 : (mat == 4) ? w4 : w5;
    float v = W[k * 128 + n];
    __half hi = __float2half_rn(v);
    __half lo = __float2half_rn(v - __half2float(hi));
    __half* dst = g_wb + (size_t)mat * 128 * 256 + (size_t)n * 256;
    dst[k] = hi;
    dst[128 + k] = lo;
}

// ---------------- aggregation: fp16 gather, fp32 accumulate, fp16 out ----------------
__global__ void k_agg(int layer) {
    int gw = (blockIdx.x * blockDim.x + threadIdx.x) >> 5;
    if (gw >= NN) return;
    int lane = threadIdx.x & 31;
    const __half* xin = (layer == 0) ? g_x16 : (g_xs16 + (size_t)(layer - 1) * NN * DD);
    const uint2* x2 = (const uint2*)xin;   // 4 halves per lane, 32 lanes = 256B row

    float4 acc = h4tof4(x2[(size_t)gw * 32 + lane]);
    int j = g_off[gw];
    int end = g_off[gw + 1];
    for (; j + 3 < end; j += 4) {
        int s0 = g_srcs[j], s1 = g_srcs[j + 1], s2 = g_srcs[j + 2], s3 = g_srcs[j + 3];
        uint2 ua = __ldg(&x2[(size_t)s0 * 32 + lane]);
        uint2 ub = __ldg(&x2[(size_t)s1 * 32 + lane]);
        uint2 uc = __ldg(&x2[(size_t)s2 * 32 + lane]);
        uint2 ud = __ldg(&x2[(size_t)s3 * 32 + lane]);
        float4 a = h4tof4(ua), b = h4tof4(ub), c = h4tof4(uc), d = h4tof4(ud);
        acc.x += (a.x + b.x) + (c.x + d.x);
        acc.y += (a.y + b.y) + (c.y + d.y);
        acc.z += (a.z + b.z) + (c.z + d.z);
        acc.w += (a.w + b.w) + (c.w + d.w);
    }
    for (; j < end; j++) {
        float4 a = h4tof4(__ldg(&x2[(size_t)g_srcs[j] * 32 + lane]));
        acc.x += a.x; acc.y += a.y; acc.z += a.z; acc.w += a.w;
    }
    uint2 o;
    *(__half2*)&o.x = __floats2half2_rn(acc.x, acc.y);
    *(__half2*)&o.y = __floats2half2_rn(acc.z, acc.w);
    ((uint2*)g_agg16)[(size_t)gw * 32 + lane] = o;
}

// ---------------- f16 mma.sync MLP: 128x128 tile per CTA, 2-term W split ----------------
// smem: A @0 (128 rows x 256B = 32KB), W1 @32768 (64KB), W2 @98304 (64KB)
#define SW1_OFF 32768u
#define SW2_OFF 98304u
#define SMEM_MLP 163840

__global__ __launch_bounds__(256)
void k_mlp(const float* __restrict__ b1, const float* __restrict__ b2, int layer)
{
    extern __shared__ char smem[];
    const uint32_t sa = smem_u32(smem);
    const int tid = threadIdx.x, wid = tid >> 5, lane = tid & 31;
    const int base = blockIdx.x * 128;
    const int wm = wid & 3, wn = wid >> 2;
    const int m0w = wm * 32;            // warp's 32 rows
    const int ncol0 = wn * 64;          // warp's 64 cols
    const int lr = lane & 7, grp = lane >> 3;
    const __half* wb1 = g_wb + (size_t)(layer * 2)     * 128 * 256;
    const __half* wb2 = g_wb + (size_t)(layer * 2 + 1) * 128 * 256;

    // ---- A tile: raw fp16 copy from g_agg16 into swizzled smem (exact) ----
    {
        const uint2* in2 = (const uint2*)g_agg16;
        int kb = lane * 8;   // 4 fp16 = 8 bytes per lane
#pragma unroll 4
        for (int it = 0; it < 16; it++) {
            int m = wid + it * 8;
            int node = base + m;
            uint2 v = make_uint2(0u, 0u);
            if (node < NN) v = in2[(size_t)node * 32 + lane];
            *(uint2*)(smem + swsA(m, kb)) = v;
        }
    }
    // ---- W1/W2 (fp16 hi|lo, 512B rows) into swizzled smem ----
    {
        int kb = lane * 16;
#pragma unroll 4
        for (int it = 0; it < 16; it++) {
            int n = wid + it * 8;
            uint4 r1 = ((const uint4*)(wb1 + (size_t)n * 256))[lane];
            uint4 r2 = ((const uint4*)(wb2 + (size_t)n * 256))[lane];
            uint32_t o = sws(n, kb);
            *(uint4*)(smem + SW1_OFF + o) = r1;
            *(uint4*)(smem + SW2_OFF + o) = r2;
        }
    }
    __syncthreads();

    const int arow = lr + ((grp & 1) << 3);
    const int akadd = (grp & 2) ? 16 : 0;
    const int brow = lr + ((grp & 2) << 2);
    const int bkadd = (grp & 1) ? 16 : 0;
    const uint32_t lxor = (uint32_t)(lr << 4);
    uint32_t abase[2], bbase[4];
#pragma unroll
    for (int i = 0; i < 2; i++) abase[i] = sa + (uint32_t)((m0w + 16 * i + arow) * 256);
#pragma unroll
    for (int j = 0; j < 4; j++) bbase[j] = (uint32_t)((ncol0 + 16 * j + brow) * 512);

    float c[2][8][4];

#pragma unroll 1
    for (int g = 0; g < 2; g++) {
        const uint32_t woff = sa + (g == 0 ? SW1_OFF : SW2_OFF);
#pragma unroll
        for (int i = 0; i < 2; i++)
#pragma unroll
            for (int j = 0; j < 8; j++)
#pragma unroll
                for (int q = 0; q < 4; q++) c[i][j][q] = 0.f;

        // 2 W-split terms x 8 k-steps
#pragma unroll 1
        for (int t = 0; t < 2; t++) {
            const int bkoff = (t == 1) ? 256 : 0;
#pragma unroll
            for (int ks = 0; ks < 8; ks++) {
                const int kb = ks * 32;
                uint32_t fa[2][4], fb[8][2];
#pragma unroll
                for (int i = 0; i < 2; i++)
                    ldsm4(fa[i][0], fa[i][1], fa[i][2], fa[i][3],
                          abase[i] + (uint32_t)((kb + akadd) ^ lxor));
#pragma unroll
                for (int jj = 0; jj < 4; jj++) {
                    uint32_t r0, r1, r2, r3;
                    ldsm4(r0, r1, r2, r3,
                          woff + bbase[jj] + (uint32_t)((kb + bkoff + bkadd) ^ lxor));
                    fb[2 * jj][0] = r0; fb[2 * jj][1] = r1;
                    fb[2 * jj + 1][0] = r2; fb[2 * jj + 1][1] = r3;
                }
#pragma unroll
                for (int i = 0; i < 2; i++)
#pragma unroll
                    for (int j = 0; j < 8; j++)
                        mma16816(c[i][j], fa[i], fb[j]);
            }
        }

        if (g == 0) {
            // epilogue 1: bias + relu, store h (fp16) back into A smem
            __syncthreads();   // all warps done reading A
#pragma unroll
            for (int j = 0; j < 8; j++) {
                int n = ncol0 + 8 * j + 2 * (lane & 3);
                float bn0 = __ldg(&b1[n]), bn1 = __ldg(&b1[n + 1]);
#pragma unroll
                for (int i = 0; i < 2; i++) {
                    int r0 = m0w + 16 * i + (lane >> 2);
                    float h0 = fmaxf(c[i][j][0] + bn0, 0.f);
                    float h1 = fmaxf(c[i][j][1] + bn1, 0.f);
                    float h2 = fmaxf(c[i][j][2] + bn0, 0.f);
                    float h3 = fmaxf(c[i][j][3] + bn1, 0.f);
                    *(uint32_t*)(smem + swsA(r0, 2 * n))     = packh2(h0, h1);
                    *(uint32_t*)(smem + swsA(r0 + 8, 2 * n)) = packh2(h2, h3);
                }
            }
            __syncthreads();
        }
    }

    // ---- epilogue 2: bias (+relu), write fp16 g_xs16[layer] ----
    {
        const int relu_out = (layer < 2);
        __half* outp = g_xs16 + (size_t)layer * NN * DD;
#pragma unroll
        for (int j = 0; j < 8; j++) {
            int n = ncol0 + 8 * j + 2 * (lane & 3);
            float bn0 = __ldg(&b2[n]), bn1 = __ldg(&b2[n + 1]);
#pragma unroll
            for (int i = 0; i < 2; i++) {
                int r0 = base + m0w + 16 * i + (lane >> 2);
                float o0 = c[i][j][0] + bn0, o1 = c[i][j][1] + bn1;
                float o2 = c[i][j][2] + bn0, o3 = c[i][j][3] + bn1;
                if (relu_out) {
                    o0 = fmaxf(o0, 0.f); o1 = fmaxf(o1, 0.f);
                    o2 = fmaxf(o2, 0.f); o3 = fmaxf(o3, 0.f);
                }
                if (r0 < NN)
                    *(__half2*)(outp + (size_t)r0 * DD + n) = __floats2half2_rn(o0, o1);
                if (r0 + 8 < NN)
                    *(__half2*)(outp + (size_t)(r0 + 8) * DD + n) = __floats2half2_rn(o2, o3);
            }
        }
    }
}

// ---------------- readout: fp16 activations ----------------
__global__ void k_readout(const float* __restrict__ Wm, const float* __restrict__ bm,
                          float* __restrict__ out) {
    int gw = (blockIdx.x * blockDim.x + threadIdx.x) >> 5;
    if (gw >= NN) return;
    int lane = threadIdx.x & 31;
    float acc = 0.f;
#pragma unroll
    for (int l = 0; l < 3; l++) {
        const uint2* xs2 = (const uint2*)(g_xs16 + (size_t)l * NN * DD);
        float4 v = h4tof4(xs2[(size_t)gw * 32 + lane]);
        float4 w = __ldg(&((const float4*)(Wm + l * 128))[lane]);
        acc += v.x * w.x + v.y * w.y + v.z * w.z + v.w * w.w;
    }
#pragma unroll
    for (int o = 16; o; o >>= 1) acc += __shfl_xor_sync(0xffffffffu, acc, o);
    if (lane == 0) {
        float z = acc + __ldg(bm);
        out[gw] = 1.0f / (1.0f + expf(-z));
    }
}

// ---------------- launch ----------------
extern "C" void kernel_launch(void* const* d_in, const int* in_sizes, int n_in,
                              void* d_out, int out_size) {
    const float* x  = (const float*)d_in[0];
    const int*   ei = (const int*)d_in[1];
    const float* W1[3] = {(const float*)d_in[3],  (const float*)d_in[7],  (const float*)d_in[11]};
    const float* b1[3] = {(const float*)d_in[4],  (const float*)d_in[8],  (const float*)d_in[12]};
    const float* W2[3] = {(const float*)d_in[5],  (const float*)d_in[9],  (const float*)d_in[13]};
    const float* b2[3] = {(const float*)d_in[6],  (const float*)d_in[10], (const float*)d_in[14]};
    const float* Wm = (const float*)d_in[15];
    const float* bm = (const float*)d_in[16];
    float* out = (float*)d_out;

    cudaFuncSetAttribute(k_mlp, cudaFuncAttributeMaxDynamicSharedMemorySize, SMEM_MLP);

    // CSR build + prep (deterministic every launch)
    k_detect<<<1, 32>>>(ei);
    k_zero<<<(NN + 255) / 256, 256>>>();
    k_hist<<<(NE + 255) / 256, 256>>>(ei);
    k_scan1<<<NSB, SCAN_BLK>>>();
    k_scan2<<<1, 128>>>();
    k_scan3<<<NSB, SCAN_BLK>>>();
    k_scatter<<<(NE + 255) / 256, 256>>>(ei);
    k_wprep<<<(6 * 128 * 128 + 255) / 256, 256>>>(W1[0], W2[0], W1[1], W2[1], W1[2], W2[2]);
    k_xprep<<<(NN * DD / 4 + 255) / 256, 256>>>(x);

    const int AGG_BLOCKS = (NN * 32 + 255) / 256;   // 12500
    const int MLP_BLOCKS = (NN + 127) / 128;        // 782

    for (int l = 0; l < 3; l++) {
        k_agg<<<AGG_BLOCKS, 256>>>(l);
        k_mlp<<<MLP_BLOCKS, 256, SMEM_MLP>>>(b1[l], b2[l], l);
    }
    k_readout<<<AGG_BLOCKS, 256>>>(Wm, bm, out);
}

// round 15
// speedup vs baseline: 1.3067x; 1.0682x over previous
#include <cuda_runtime.h>
#include <cuda_bf16.h>
#include <cuda_fp16.h>
#include <stdint.h>
#include <math.h>

#define NN 100000
#define NE 1600000
#define DD 128
#define SCAN_BLK 1024
#define NSB ((NN + SCAN_BLK - 1) / SCAN_BLK)   // 98 scan blocks

// ---------------- scratch (device globals; no allocation) ----------------
__device__ alignas(16) __half g_agg16[(size_t)NN * DD];       // 25.6 MB (fp16 MLP input)
__device__ alignas(16) __half g_x16[(size_t)NN * DD];         // 25.6 MB (fp16 input copy)
__device__ alignas(16) __half g_xs16[(size_t)3 * NN * DD];    // 76.8 MB (fp16 layer outputs)
__device__ alignas(16) __half g_wb[6 * 128 * 256];            // fp16 split weights [mat][n][k: hi|lo]
__device__ alignas(16) int   g_deg[NN];
__device__ alignas(16) int   g_cur[NN];
__device__ alignas(16) int   g_srcs[NE];
__device__ alignas(16) int   g_off[NN + 1];
__device__ alignas(16) int   g_bsum[NSB];
__device__ alignas(16) int   g_bpre[NSB];
__device__ int g_is64;

__device__ __forceinline__ uint32_t smem_u32(const void* p) {
    uint32_t a;
    asm("{ .reg .u64 t; cvta.to.shared.u64 t, %1; cvt.u32.u64 %0, t; }" : "=r"(a) : "l"(p));
    return a;
}
__device__ __forceinline__ void ldsm4(uint32_t& r0, uint32_t& r1, uint32_t& r2, uint32_t& r3, uint32_t addr) {
    asm volatile("ldmatrix.sync.aligned.m8n8.x4.shared.b16 {%0,%1,%2,%3}, [%4];"
                 : "=r"(r0), "=r"(r1), "=r"(r2), "=r"(r3) : "r"(addr));
}
__device__ __forceinline__ void mma16816(float* c, const uint32_t* a, const uint32_t* b) {
    asm volatile("mma.sync.aligned.m16n8k16.row.col.f32.f16.f16.f32 "
                 "{%0,%1,%2,%3}, {%4,%5,%6,%7}, {%8,%9}, {%0,%1,%2,%3};"
                 : "+f"(c[0]), "+f"(c[1]), "+f"(c[2]), "+f"(c[3])
                 : "r"(a[0]), "r"(a[1]), "r"(a[2]), "r"(a[3]), "r"(b[0]), "r"(b[1]));
}
// swizzled smem byte offset within a 512B row (W: k hi bytes 0-255, lo 256-511)
__device__ __forceinline__ uint32_t sws(int row, int kb) {
    return (uint32_t)(row * 512 + (kb ^ ((row & 7) << 4)));
}
// swizzled smem byte offset within a 256B fp16 row (A: 128 fp16)
__device__ __forceinline__ uint32_t swsA(int row, int kb) {
    return (uint32_t)(row * 256 + (kb ^ ((row & 7) << 4)));
}
__device__ __forceinline__ float4 h4tof4(uint2 u) {
    __half2 h0 = *(__half2*)&u.x, h1 = *(__half2*)&u.y;
    float2 f0 = __half22float2(h0), f1 = __half22float2(h1);
    return make_float4(f0.x, f0.y, f1.x, f1.y);
}
__device__ __forceinline__ uint32_t packh2(float a, float b) {
    __half2 h = __floats2half2_rn(a, b);
    return *(uint32_t*)&h;
}

// ---------------- prep0: detect dtype + zero degree ----------------
__global__ void k_prep0(const int* __restrict__ ei32) {
    int i = blockIdx.x * blockDim.x + threadIdx.x;
    if (i < NN) g_deg[i] = 0;
    if (blockIdx.x == 0 && threadIdx.x < 32) {
        int lane = threadIdx.x;
        int nz = 0;
#pragma unroll
        for (int k = 0; k < 2; k++) {
            int w = ei32[2 * (lane + 32 * k) + 1];
            nz |= (w != 0);
        }
        unsigned any = __ballot_sync(0xffffffffu, nz);
        if (lane == 0) g_is64 = (any == 0u) ? 1 : 0;
    }
}

// ---------------- prep1: x fp32->fp16 + weight split ----------------
__global__ void k_prep1(const float* __restrict__ x,
                        const float* __restrict__ w0, const float* __restrict__ w1,
                        const float* __restrict__ w2, const float* __restrict__ w3,
                        const float* __restrict__ w4, const float* __restrict__ w5) {
    int i = blockIdx.x * blockDim.x + threadIdx.x;
    if (i < NN * DD / 4) {
        float4 v = ((const float4*)x)[i];
        ((__half2*)g_x16)[2 * i]     = __floats2half2_rn(v.x, v.y);
        ((__half2*)g_x16)[2 * i + 1] = __floats2half2_rn(v.z, v.w);
    }
    if (i < 6 * 128 * 128) {
        int mat = i >> 14;
        int k = (i >> 7) & 127;
        int n = i & 127;
        const float* W = (mat == 0) ? w0 : (mat == 1) ? w1 : (mat == 2) ? w2
                       : (mat == 3) ? w3 : (mat == 4) ? w4 : w5;
        float v = W[k * 128 + n];
        __half hi = __float2half_rn(v);
        __half lo = __float2half_rn(v - __half2float(hi));
        __half* dst = g_wb + (size_t)mat * 128 * 256 + (size_t)n * 256;
        dst[k] = hi;
        dst[128 + k] = lo;
    }
}

// ---------------- CSR build ----------------
__global__ void k_hist(const int* __restrict__ ei32) {
    int e = blockIdx.x * blockDim.x + threadIdx.x;
    if (e < NE) {
        int is64 = g_is64;
        unsigned d = is64 ? (unsigned)ei32[2 * (NE + e)] : (unsigned)ei32[NE + e];
        if (d < NN) atomicAdd(&g_deg[d], 1);
    }
}
__global__ void k_scan1() {
    __shared__ int ws[32];
    int i = blockIdx.x * SCAN_BLK + threadIdx.x;
    int v = (i < NN) ? g_deg[i] : 0;
    int s = v;
#pragma unroll
    for (int o = 16; o; o >>= 1) s += __shfl_xor_sync(0xffffffffu, s, o);
    if ((threadIdx.x & 31) == 0) ws[threadIdx.x >> 5] = s;
    __syncthreads();
    if (threadIdx.x < 32) {
        int t = ws[threadIdx.x];
#pragma unroll
        for (int o = 16; o; o >>= 1) t += __shfl_xor_sync(0xffffffffu, t, o);
        if (threadIdx.x == 0) g_bsum[blockIdx.x] = t;
    }
}
__global__ void k_scan2() {
    __shared__ int warp_incl[4];
    int t = threadIdx.x;
    int v = (t < NSB) ? g_bsum[t] : 0;
    int incl = v;
#pragma unroll
    for (int o = 1; o < 32; o <<= 1) {
        int u = __shfl_up_sync(0xffffffffu, incl, o);
        if ((t & 31) >= o) incl += u;
    }
    if ((t & 31) == 31) warp_incl[t >> 5] = incl;
    __syncthreads();
    int base = 0;
#pragma unroll
    for (int w = 0; w < 4; w++)
        if ((t >> 5) > w) base += warp_incl[w];
    incl += base;
    if (t < NSB) g_bpre[t] = incl - v;
    if (t == NSB - 1) g_off[NN] = incl;
}
__global__ void k_scan3() {
    __shared__ int wsum[32];
    int t = threadIdx.x;
    int i = blockIdx.x * SCAN_BLK + t;
    int v = (i < NN) ? g_deg[i] : 0;
    int lane = t & 31, wrp = t >> 5;
    int incl = v;
#pragma unroll
    for (int o = 1; o < 32; o <<= 1) {
        int u = __shfl_up_sync(0xffffffffu, incl, o);
        if (lane >= o) incl += u;
    }
    if (lane == 31) wsum[wrp] = incl;
    __syncthreads();
    if (wrp == 0) {
        int w = wsum[lane];
        int wincl = w;
#pragma unroll
        for (int o = 1; o < 32; o <<= 1) {
            int u = __shfl_up_sync(0xffffffffu, wincl, o);
            if (lane >= o) wincl += u;
        }
        wsum[lane] = wincl - w;
    }
    __syncthreads();
    if (i < NN) {
        int off = g_bpre[blockIdx.x] + wsum[wrp] + incl - v;
        g_off[i] = off;
        g_cur[i] = off;
    }
}
__global__ void k_scatter(const int* __restrict__ ei32) {
    int e = blockIdx.x * blockDim.x + threadIdx.x;
    if (e < NE) {
        int is64 = g_is64;
        unsigned d    = is64 ? (unsigned)ei32[2 * (NE + e)] : (unsigned)ei32[NE + e];
        unsigned srcv = is64 ? (unsigned)ei32[2 * e]        : (unsigned)ei32[e];
        if (d < NN && srcv < NN) {
            int pos = atomicAdd(&g_cur[d], 1);
            g_srcs[pos] = (int)srcv;
        }
    }
}

// ---------------- aggregation: fp16 gather, fp32 accumulate, fp16 out ----------------
__global__ void k_agg(int layer) {
    int gw = (blockIdx.x * blockDim.x + threadIdx.x) >> 5;
    if (gw >= NN) return;
    int lane = threadIdx.x & 31;
    const __half* xin = (layer == 0) ? g_x16 : (g_xs16 + (size_t)(layer - 1) * NN * DD);
    const uint2* x2 = (const uint2*)xin;   // 4 halves per lane, 32 lanes = 256B row

    float4 acc = h4tof4(x2[(size_t)gw * 32 + lane]);
    int j = g_off[gw];
    int end = g_off[gw + 1];
    for (; j + 3 < end; j += 4) {
        int s0 = g_srcs[j], s1 = g_srcs[j + 1], s2 = g_srcs[j + 2], s3 = g_srcs[j + 3];
        uint2 ua = __ldg(&x2[(size_t)s0 * 32 + lane]);
        uint2 ub = __ldg(&x2[(size_t)s1 * 32 + lane]);
        uint2 uc = __ldg(&x2[(size_t)s2 * 32 + lane]);
        uint2 ud = __ldg(&x2[(size_t)s3 * 32 + lane]);
        float4 a = h4tof4(ua), b = h4tof4(ub), c = h4tof4(uc), d = h4tof4(ud);
        acc.x += (a.x + b.x) + (c.x + d.x);
        acc.y += (a.y + b.y) + (c.y + d.y);
        acc.z += (a.z + b.z) + (c.z + d.z);
        acc.w += (a.w + b.w) + (c.w + d.w);
    }
    for (; j < end; j++) {
        float4 a = h4tof4(__ldg(&x2[(size_t)g_srcs[j] * 32 + lane]));
        acc.x += a.x; acc.y += a.y; acc.z += a.z; acc.w += a.w;
    }
    uint2 o;
    *(__half2*)&o.x = __floats2half2_rn(acc.x, acc.y);
    *(__half2*)&o.y = __floats2half2_rn(acc.z, acc.w);
    ((uint2*)g_agg16)[(size_t)gw * 32 + lane] = o;
}

// ---------------- f16 mma.sync MLP: 256x128 tile per CTA, 2-term W split ----------------
// smem: A @0 (256 rows x 256B = 64KB), W1 @65536 (64KB), W2 @131072 (64KB)
#define SW1_OFF 65536u
#define SW2_OFF 131072u
#define SMEM_MLP 196608

__global__ __launch_bounds__(256)
void k_mlp(const float* __restrict__ b1, const float* __restrict__ b2, int layer)
{
    extern __shared__ char smem[];
    const uint32_t sa = smem_u32(smem);
    const int tid = threadIdx.x, wid = tid >> 5, lane = tid & 31;
    const int base = blockIdx.x * 256;
    const int wm = wid & 3, wn = wid >> 2;
    const int m0w = wm * 64;            // warp's 64 rows
    const int ncol0 = wn * 64;          // warp's 64 cols
    const int lr = lane & 7, grp = lane >> 3;
    const __half* wb1 = g_wb + (size_t)(layer * 2)     * 128 * 256;
    const __half* wb2 = g_wb + (size_t)(layer * 2 + 1) * 128 * 256;

    // ---- A tile: raw fp16 copy from g_agg16 into swizzled smem (exact) ----
    {
        const uint2* in2 = (const uint2*)g_agg16;
        int kb = lane * 8;
#pragma unroll 4
        for (int it = 0; it < 32; it++) {
            int m = wid + it * 8;         // 0..255
            int node = base + m;
            uint2 v = make_uint2(0u, 0u);
            if (node < NN) v = in2[(size_t)node * 32 + lane];
            *(uint2*)(smem + swsA(m, kb)) = v;
        }
    }
    // ---- W1/W2 (fp16 hi|lo, 512B rows) into swizzled smem ----
    {
        int kb = lane * 16;
#pragma unroll 4
        for (int it = 0; it < 16; it++) {
            int n = wid + it * 8;
            uint4 r1 = ((const uint4*)(wb1 + (size_t)n * 256))[lane];
            uint4 r2 = ((const uint4*)(wb2 + (size_t)n * 256))[lane];
            uint32_t o = sws(n, kb);
            *(uint4*)(smem + SW1_OFF + o) = r1;
            *(uint4*)(smem + SW2_OFF + o) = r2;
        }
    }
    __syncthreads();

    const int arow = lr + ((grp & 1) << 3);
    const int akadd = (grp & 2) ? 16 : 0;
    const int brow = lr + ((grp & 2) << 2);
    const int bkadd = (grp & 1) ? 16 : 0;
    const uint32_t lxor = (uint32_t)(lr << 4);
    uint32_t abase[4], bbase[4];
#pragma unroll
    for (int i = 0; i < 4; i++) abase[i] = sa + (uint32_t)((m0w + 16 * i + arow) * 256);
#pragma unroll
    for (int j = 0; j < 4; j++) bbase[j] = (uint32_t)((ncol0 + 16 * j + brow) * 512);

    float c[4][8][4];

#pragma unroll 1
    for (int g = 0; g < 2; g++) {
        const uint32_t woff = sa + (g == 0 ? SW1_OFF : SW2_OFF);
#pragma unroll
        for (int i = 0; i < 4; i++)
#pragma unroll
            for (int j = 0; j < 8; j++)
#pragma unroll
                for (int q = 0; q < 4; q++) c[i][j][q] = 0.f;

        // 2 W-split terms x 8 k-steps
#pragma unroll 1
        for (int t = 0; t < 2; t++) {
            const int bkoff = (t == 1) ? 256 : 0;
#pragma unroll
            for (int ks = 0; ks < 8; ks++) {
                const int kb = ks * 32;
                uint32_t fa[4][4], fb[8][2];
#pragma unroll
                for (int i = 0; i < 4; i++)
                    ldsm4(fa[i][0], fa[i][1], fa[i][2], fa[i][3],
                          abase[i] + (uint32_t)((kb + akadd) ^ lxor));
#pragma unroll
                for (int jj = 0; jj < 4; jj++) {
                    uint32_t r0, r1, r2, r3;
                    ldsm4(r0, r1, r2, r3,
                          woff + bbase[jj] + (uint32_t)((kb + bkoff + bkadd) ^ lxor));
                    fb[2 * jj][0] = r0; fb[2 * jj][1] = r1;
                    fb[2 * jj + 1][0] = r2; fb[2 * jj + 1][1] = r3;
                }
#pragma unroll
                for (int i = 0; i < 4; i++)
#pragma unroll
                    for (int j = 0; j < 8; j++)
                        mma16816(c[i][j], fa[i], fb[j]);
            }
        }

        if (g == 0) {
            // epilogue 1: bias + relu, store h (fp16) back into A smem
            __syncthreads();
#pragma unroll
            for (int j = 0; j < 8; j++) {
                int n = ncol0 + 8 * j + 2 * (lane & 3);
                float bn0 = __ldg(&b1[n]), bn1 = __ldg(&b1[n + 1]);
#pragma unroll
                for (int i = 0; i < 4; i++) {
                    int r0 = m0w + 16 * i + (lane >> 2);
                    float h0 = fmaxf(c[i][j][0] + bn0, 0.f);
                    float h1 = fmaxf(c[i][j][1] + bn1, 0.f);
                    float h2 = fmaxf(c[i][j][2] + bn0, 0.f);
                    float h3 = fmaxf(c[i][j][3] + bn1, 0.f);
                    *(uint32_t*)(smem + swsA(r0, 2 * n))     = packh2(h0, h1);
                    *(uint32_t*)(smem + swsA(r0 + 8, 2 * n)) = packh2(h2, h3);
                }
            }
            __syncthreads();
        }
    }

    // ---- epilogue 2: bias (+relu), write fp16 g_xs16[layer] ----
    {
        const int relu_out = (layer < 2);
        __half* outp = g_xs16 + (size_t)layer * NN * DD;
#pragma unroll
        for (int j = 0; j < 8; j++) {
            int n = ncol0 + 8 * j + 2 * (lane & 3);
            float bn0 = __ldg(&b2[n]), bn1 = __ldg(&b2[n + 1]);
#pragma unroll
            for (int i = 0; i < 4; i++) {
                int r0 = base + m0w + 16 * i + (lane >> 2);
                float o0 = c[i][j][0] + bn0, o1 = c[i][j][1] + bn1;
                float o2 = c[i][j][2] + bn0, o3 = c[i][j][3] + bn1;
                if (relu_out) {
                    o0 = fmaxf(o0, 0.f); o1 = fmaxf(o1, 0.f);
                    o2 = fmaxf(o2, 0.f); o3 = fmaxf(o3, 0.f);
                }
                if (r0 < NN)
                    *(__half2*)(outp + (size_t)r0 * DD + n) = __floats2half2_rn(o0, o1);
                if (r0 + 8 < NN)
                    *(__half2*)(outp + (size_t)(r0 + 8) * DD + n) = __floats2half2_rn(o2, o3);
            }
        }
    }
}

// ---------------- readout: fp16 activations ----------------
__global__ void k_readout(const float* __restrict__ Wm, const float* __restrict__ bm,
                          float* __restrict__ out) {
    int gw = (blockIdx.x * blockDim.x + threadIdx.x) >> 5;
    if (gw >= NN) return;
    int lane = threadIdx.x & 31;
    float acc = 0.f;
#pragma unroll
    for (int l = 0; l < 3; l++) {
        const uint2* xs2 = (const uint2*)(g_xs16 + (size_t)l * NN * DD);
        float4 v = h4tof4(xs2[(size_t)gw * 32 + lane]);
        float4 w = __ldg(&((const float4*)(Wm + l * 128))[lane]);
        acc += v.x * w.x + v.y * w.y + v.z * w.z + v.w * w.w;
    }
#pragma unroll
    for (int o = 16; o; o >>= 1) acc += __shfl_xor_sync(0xffffffffu, acc, o);
    if (lane == 0) {
        float z = acc + __ldg(bm);
        out[gw] = 1.0f / (1.0f + expf(-z));
    }
}

// ---------------- launch ----------------
extern "C" void kernel_launch(void* const* d_in, const int* in_sizes, int n_in,
                              void* d_out, int out_size) {
    const float* x  = (const float*)d_in[0];
    const int*   ei = (const int*)d_in[1];
    const float* W1[3] = {(const float*)d_in[3],  (const float*)d_in[7],  (const float*)d_in[11]};
    const float* b1[3] = {(const float*)d_in[4],  (const float*)d_in[8],  (const float*)d_in[12]};
    const float* W2[3] = {(const float*)d_in[5],  (const float*)d_in[9],  (const float*)d_in[13]};
    const float* b2[3] = {(const float*)d_in[6],  (const float*)d_in[10], (const float*)d_in[14]};
    const float* Wm = (const float*)d_in[15];
    const float* bm = (const float*)d_in[16];
    float* out = (float*)d_out;

    cudaFuncSetAttribute(k_mlp, cudaFuncAttributeMaxDynamicSharedMemorySize, SMEM_MLP);

    // CSR build + prep (deterministic every launch)
    k_prep0<<<(NN + 255) / 256, 256>>>(ei);
    k_hist<<<(NE + 255) / 256, 256>>>(ei);
    k_scan1<<<NSB, SCAN_BLK>>>();
    k_scan2<<<1, 128>>>();
    k_scan3<<<NSB, SCAN_BLK>>>();
    k_scatter<<<(NE + 255) / 256, 256>>>(ei);
    k_prep1<<<(NN * DD / 4 + 255) / 256, 256>>>(x, W1[0], W2[0], W1[1], W2[1], W1[2], W2[2]);

    const int AGG_BLOCKS = (NN * 32 + 255) / 256;   // 12500
    const int MLP_BLOCKS = (NN + 255) / 256;        // 391

    for (int l = 0; l < 3; l++) {
        k_agg<<<AGG_BLOCKS, 256>>>(l);
        k_mlp<<<MLP_BLOCKS, 256, SMEM_MLP>>>(b1[l], b2[l], l);
    }
    k_readout<<<AGG_BLOCKS, 256>>>(Wm, bm, out);
}

// round 16
// speedup vs baseline: 1.3229x; 1.0124x over previous
#include <cuda_runtime.h>
#include <cuda_bf16.h>
#include <cuda_fp16.h>
#include <stdint.h>
#include <math.h>

#define NN 100000
#define NE 1600000
#define DD 128
#define SCAN_BLK 1024
#define NSB ((NN + SCAN_BLK - 1) / SCAN_BLK)   // 98 scan blocks

// ---------------- scratch (device globals; no allocation) ----------------
__device__ alignas(16) __half g_agg16[(size_t)NN * DD];       // 25.6 MB (fp16 MLP input)
__device__ alignas(16) __half g_x16[(size_t)NN * DD];         // 25.6 MB (fp16 input copy)
__device__ alignas(16) __half g_xs16[(size_t)3 * NN * DD];    // 76.8 MB (fp16 layer outputs)
__device__ alignas(16) __half g_wb[6 * 128 * 256];            // fp16 split weights [mat][n][k: hi|lo]
__device__ alignas(16) int   g_deg[NN];
__device__ alignas(16) int   g_cur[NN];
__device__ alignas(16) int   g_srcs[NE];
__device__ alignas(16) int   g_off[NN + 1];
__device__ alignas(16) int   g_bsum[NSB];

__device__ __forceinline__ uint32_t smem_u32(const void* p) {
    uint32_t a;
    asm("{ .reg .u64 t; cvta.to.shared.u64 t, %1; cvt.u32.u64 %0, t; }" : "=r"(a) : "l"(p));
    return a;
}
__device__ __forceinline__ void ldsm4(uint32_t& r0, uint32_t& r1, uint32_t& r2, uint32_t& r3, uint32_t addr) {
    asm volatile("ldmatrix.sync.aligned.m8n8.x4.shared.b16 {%0,%1,%2,%3}, [%4];"
                 : "=r"(r0), "=r"(r1), "=r"(r2), "=r"(r3) : "r"(addr));
}
__device__ __forceinline__ void mma16816(float* c, const uint32_t* a, const uint32_t* b) {
    asm volatile("mma.sync.aligned.m16n8k16.row.col.f32.f16.f16.f32 "
                 "{%0,%1,%2,%3}, {%4,%5,%6,%7}, {%8,%9}, {%0,%1,%2,%3};"
                 : "+f"(c[0]), "+f"(c[1]), "+f"(c[2]), "+f"(c[3])
                 : "r"(a[0]), "r"(a[1]), "r"(a[2]), "r"(a[3]), "r"(b[0]), "r"(b[1]));
}
// swizzled smem byte offset within a 512B row (W: k hi bytes 0-255, lo 256-511)
__device__ __forceinline__ uint32_t sws(int row, int kb) {
    return (uint32_t)(row * 512 + (kb ^ ((row & 7) << 4)));
}
// swizzled smem byte offset within a 256B fp16 row (A: 128 fp16)
__device__ __forceinline__ uint32_t swsA(int row, int kb) {
    return (uint32_t)(row * 256 + (kb ^ ((row & 7) << 4)));
}
__device__ __forceinline__ float4 h4tof4(uint2 u) {
    __half2 h0 = *(__half2*)&u.x, h1 = *(__half2*)&u.y;
    float2 f0 = __half22float2(h0), f1 = __half22float2(h1);
    return make_float4(f0.x, f0.y, f1.x, f1.y);
}
__device__ __forceinline__ uint32_t packh2(float a, float b) {
    __half2 h = __floats2half2_rn(a, b);
    return *(uint32_t*)&h;
}
// per-block int64-vs-int32 probe: high words of first 64 src entries all zero => int64
__device__ __forceinline__ int probe_is64(const int* __restrict__ ei32, int lane) {
    int nz = 0;
#pragma unroll
    for (int k = 0; k < 2; k++) {
        int w = __ldg(&ei32[2 * (lane + 32 * k) + 1]);
        nz |= (w != 0);
    }
    unsigned any = __ballot_sync(0xffffffffu, nz);
    return (any == 0u) ? 1 : 0;
}

// ---------------- prep: zero deg + x fp32->fp16 + weight split (one kernel) ----------------
__global__ void k_prep(const float* __restrict__ x,
                       const float* __restrict__ w0, const float* __restrict__ w1,
                       const float* __restrict__ w2, const float* __restrict__ w3,
                       const float* __restrict__ w4, const float* __restrict__ w5) {
    int i = blockIdx.x * blockDim.x + threadIdx.x;
    if (i < NN) g_deg[i] = 0;
    if (i < NN * DD / 4) {
        float4 v = ((const float4*)x)[i];
        ((__half2*)g_x16)[2 * i]     = __floats2half2_rn(v.x, v.y);
        ((__half2*)g_x16)[2 * i + 1] = __floats2half2_rn(v.z, v.w);
    }
    if (i < 6 * 128 * 128) {
        int mat = i >> 14;
        int k = (i >> 7) & 127;
        int n = i & 127;
        const float* W = (mat == 0) ? w0 : (mat == 1) ? w1 : (mat == 2) ? w2
                       : (mat == 3) ? w3 : (mat == 4) ? w4 : w5;
        float v = W[k * 128 + n];
        __half hi = __float2half_rn(v);
        __half lo = __float2half_rn(v - __half2float(hi));
        __half* dst = g_wb + (size_t)mat * 128 * 256 + (size_t)n * 256;
        dst[k] = hi;
        dst[128 + k] = lo;
    }
}

// ---------------- CSR build ----------------
__global__ void k_hist(const int* __restrict__ ei32) {
    int is64 = probe_is64(ei32, threadIdx.x & 31);
    int e = blockIdx.x * blockDim.x + threadIdx.x;
    if (e < NE) {
        unsigned d = is64 ? (unsigned)ei32[2 * (NE + e)] : (unsigned)ei32[NE + e];
        if (d < NN) atomicAdd(&g_deg[d], 1);
    }
}
__global__ void k_scan1() {
    __shared__ int ws[32];
    int i = blockIdx.x * SCAN_BLK + threadIdx.x;
    int v = (i < NN) ? g_deg[i] : 0;
    int s = v;
#pragma unroll
    for (int o = 16; o; o >>= 1) s += __shfl_xor_sync(0xffffffffu, s, o);
    if ((threadIdx.x & 31) == 0) ws[threadIdx.x >> 5] = s;
    __syncthreads();
    if (threadIdx.x < 32) {
        int t = ws[threadIdx.x];
#pragma unroll
        for (int o = 16; o; o >>= 1) t += __shfl_xor_sync(0xffffffffu, t, o);
        if (threadIdx.x == 0) g_bsum[blockIdx.x] = t;
    }
}
// block-local scan + cross-block base computed directly from g_bsum (no scan2)
__global__ void k_scan3() {
    __shared__ int wsum[32];
    __shared__ int gbase;
    int t = threadIdx.x;
    int i = blockIdx.x * SCAN_BLK + t;
    int v = (i < NN) ? g_deg[i] : 0;
    int lane = t & 31, wrp = t >> 5;
    int incl = v;
#pragma unroll
    for (int o = 1; o < 32; o <<= 1) {
        int u = __shfl_up_sync(0xffffffffu, incl, o);
        if (lane >= o) incl += u;
    }
    if (lane == 31) wsum[wrp] = incl;
    __syncthreads();
    if (wrp == 0) {
        // warp-base scan within block
        int w = wsum[lane];
        int wincl = w;
#pragma unroll
        for (int o = 1; o < 32; o <<= 1) {
            int u = __shfl_up_sync(0xffffffffu, wincl, o);
            if (lane >= o) wincl += u;
        }
        wsum[lane] = wincl - w;
        // cross-block base: sum g_bsum[j] for j < blockIdx.x (and total for g_off[NN])
        int mybase = 0, total = 0;
        for (int j = lane; j < NSB; j += 32) {
            int b = g_bsum[j];
            total += b;
            if (j < blockIdx.x) mybase += b;
        }
#pragma unroll
        for (int o = 16; o; o >>= 1) {
            mybase += __shfl_xor_sync(0xffffffffu, mybase, o);
            total  += __shfl_xor_sync(0xffffffffu, total, o);
        }
        if (lane == 0) {
            gbase = mybase;
            if (blockIdx.x == NSB - 1) g_off[NN] = total;
        }
    }
    __syncthreads();
    if (i < NN) {
        int off = gbase + wsum[wrp] + incl - v;
        g_off[i] = off;
        g_cur[i] = off;
    }
}
__global__ void k_scatter(const int* __restrict__ ei32) {
    int is64 = probe_is64(ei32, threadIdx.x & 31);
    int e = blockIdx.x * blockDim.x + threadIdx.x;
    if (e < NE) {
        unsigned d    = is64 ? (unsigned)ei32[2 * (NE + e)] : (unsigned)ei32[NE + e];
        unsigned srcv = is64 ? (unsigned)ei32[2 * e]        : (unsigned)ei32[e];
        if (d < NN && srcv < NN) {
            int pos = atomicAdd(&g_cur[d], 1);
            g_srcs[pos] = (int)srcv;
        }
    }
}

// ---------------- aggregation: fp16 gather, fp32 accumulate, fp16 out ----------------
__global__ void k_agg(int layer) {
    int gw = (blockIdx.x * blockDim.x + threadIdx.x) >> 5;
    if (gw >= NN) return;
    int lane = threadIdx.x & 31;
    const __half* xin = (layer == 0) ? g_x16 : (g_xs16 + (size_t)(layer - 1) * NN * DD);
    const uint2* x2 = (const uint2*)xin;   // 4 halves per lane, 32 lanes = 256B row

    float4 acc = h4tof4(x2[(size_t)gw * 32 + lane]);
    int j = g_off[gw];
    int end = g_off[gw + 1];
    for (; j + 3 < end; j += 4) {
        int s0 = g_srcs[j], s1 = g_srcs[j + 1], s2 = g_srcs[j + 2], s3 = g_srcs[j + 3];
        uint2 ua = __ldg(&x2[(size_t)s0 * 32 + lane]);
        uint2 ub = __ldg(&x2[(size_t)s1 * 32 + lane]);
        uint2 uc = __ldg(&x2[(size_t)s2 * 32 + lane]);
        uint2 ud = __ldg(&x2[(size_t)s3 * 32 + lane]);
        float4 a = h4tof4(ua), b = h4tof4(ub), c = h4tof4(uc), d = h4tof4(ud);
        acc.x += (a.x + b.x) + (c.x + d.x);
        acc.y += (a.y + b.y) + (c.y + d.y);
        acc.z += (a.z + b.z) + (c.z + d.z);
        acc.w += (a.w + b.w) + (c.w + d.w);
    }
    for (; j < end; j++) {
        float4 a = h4tof4(__ldg(&x2[(size_t)g_srcs[j] * 32 + lane]));
        acc.x += a.x; acc.y += a.y; acc.z += a.z; acc.w += a.w;
    }
    uint2 o;
    *(__half2*)&o.x = __floats2half2_rn(acc.x, acc.y);
    *(__half2*)&o.y = __floats2half2_rn(acc.z, acc.w);
    ((uint2*)g_agg16)[(size_t)gw * 32 + lane] = o;
}

// ---------------- f16 mma.sync MLP: 256x128 tile per CTA, 2-term W split ----------------
// smem: A @0 (256 rows x 256B = 64KB), W1 @65536 (64KB), W2 @131072 (64KB)
#define SW1_OFF 65536u
#define SW2_OFF 131072u
#define SMEM_MLP 196608

__global__ __launch_bounds__(256)
void k_mlp(const float* __restrict__ b1, const float* __restrict__ b2, int layer)
{
    extern __shared__ char smem[];
    const uint32_t sa = smem_u32(smem);
    const int tid = threadIdx.x, wid = tid >> 5, lane = tid & 31;
    const int base = blockIdx.x * 256;
    const int wm = wid & 3, wn = wid >> 2;
    const int m0w = wm * 64;            // warp's 64 rows
    const int ncol0 = wn * 64;          // warp's 64 cols
    const int lr = lane & 7, grp = lane >> 3;
    const __half* wb1 = g_wb + (size_t)(layer * 2)     * 128 * 256;
    const __half* wb2 = g_wb + (size_t)(layer * 2 + 1) * 128 * 256;

    // ---- A tile: raw fp16 copy from g_agg16 into swizzled smem (exact) ----
    {
        const uint2* in2 = (const uint2*)g_agg16;
        int kb = lane * 8;
#pragma unroll 4
        for (int it = 0; it < 32; it++) {
            int m = wid + it * 8;         // 0..255
            int node = base + m;
            uint2 v = make_uint2(0u, 0u);
            if (node < NN) v = in2[(size_t)node * 32 + lane];
            *(uint2*)(smem + swsA(m, kb)) = v;
        }
    }
    // ---- W1/W2 (fp16 hi|lo, 512B rows) into swizzled smem ----
    {
        int kb = lane * 16;
#pragma unroll 4
        for (int it = 0; it < 16; it++) {
            int n = wid + it * 8;
            uint4 r1 = ((const uint4*)(wb1 + (size_t)n * 256))[lane];
            uint4 r2 = ((const uint4*)(wb2 + (size_t)n * 256))[lane];
            uint32_t o = sws(n, kb);
            *(uint4*)(smem + SW1_OFF + o) = r1;
            *(uint4*)(smem + SW2_OFF + o) = r2;
        }
    }
    __syncthreads();

    const int arow = lr + ((grp & 1) << 3);
    const int akadd = (grp & 2) ? 16 : 0;
    const int brow = lr + ((grp & 2) << 2);
    const int bkadd = (grp & 1) ? 16 : 0;
    const uint32_t lxor = (uint32_t)(lr << 4);
    uint32_t abase[4], bbase[4];
#pragma unroll
    for (int i = 0; i < 4; i++) abase[i] = sa + (uint32_t)((m0w + 16 * i + arow) * 256);
#pragma unroll
    for (int j = 0; j < 4; j++) bbase[j] = (uint32_t)((ncol0 + 16 * j + brow) * 512);

    float c[4][8][4];

#pragma unroll 1
    for (int g = 0; g < 2; g++) {
        const uint32_t woff = sa + (g == 0 ? SW1_OFF : SW2_OFF);
#pragma unroll
        for (int i = 0; i < 4; i++)
#pragma unroll
            for (int j = 0; j < 8; j++)
#pragma unroll
                for (int q = 0; q < 4; q++) c[i][j][q] = 0.f;

        // 2 W-split terms x 8 k-steps
#pragma unroll 1
        for (int t = 0; t < 2; t++) {
            const int bkoff = (t == 1) ? 256 : 0;
#pragma unroll
            for (int ks = 0; ks < 8; ks++) {
                const int kb = ks * 32;
                uint32_t fa[4][4], fb[8][2];
#pragma unroll
                for (int i = 0; i < 4; i++)
                    ldsm4(fa[i][0], fa[i][1], fa[i][2], fa[i][3],
                          abase[i] + (uint32_t)((kb + akadd) ^ lxor));
#pragma unroll
                for (int jj = 0; jj < 4; jj++) {
                    uint32_t r0, r1, r2, r3;
                    ldsm4(r0, r1, r2, r3,
                          woff + bbase[jj] + (uint32_t)((kb + bkoff + bkadd) ^ lxor));
                    fb[2 * jj][0] = r0; fb[2 * jj][1] = r1;
                    fb[2 * jj + 1][0] = r2; fb[2 * jj + 1][1] = r3;
                }
#pragma unroll
                for (int i = 0; i < 4; i++)
#pragma unroll
                    for (int j = 0; j < 8; j++)
                        mma16816(c[i][j], fa[i], fb[j]);
            }
        }

        if (g == 0) {
            // epilogue 1: bias + relu, store h (fp16) back into A smem
            __syncthreads();
#pragma unroll
            for (int j = 0; j < 8; j++) {
                int n = ncol0 + 8 * j + 2 * (lane & 3);
                float bn0 = __ldg(&b1[n]), bn1 = __ldg(&b1[n + 1]);
#pragma unroll
                for (int i = 0; i < 4; i++) {
                    int r0 = m0w + 16 * i + (lane >> 2);
                    float h0 = fmaxf(c[i][j][0] + bn0, 0.f);
                    float h1 = fmaxf(c[i][j][1] + bn1, 0.f);
                    float h2 = fmaxf(c[i][j][2] + bn0, 0.f);
                    float h3 = fmaxf(c[i][j][3] + bn1, 0.f);
                    *(uint32_t*)(smem + swsA(r0, 2 * n))     = packh2(h0, h1);
                    *(uint32_t*)(smem + swsA(r0 + 8, 2 * n)) = packh2(h2, h3);
                }
            }
            __syncthreads();
        }
    }

    // ---- epilogue 2: bias (+relu), write fp16 g_xs16[layer] ----
    {
        const int relu_out = (layer < 2);
        __half* outp = g_xs16 + (size_t)layer * NN * DD;
#pragma unroll
        for (int j = 0; j < 8; j++) {
            int n = ncol0 + 8 * j + 2 * (lane & 3);
            float bn0 = __ldg(&b2[n]), bn1 = __ldg(&b2[n + 1]);
#pragma unroll
            for (int i = 0; i < 4; i++) {
                int r0 = base + m0w + 16 * i + (lane >> 2);
                float o0 = c[i][j][0] + bn0, o1 = c[i][j][1] + bn1;
                float o2 = c[i][j][2] + bn0, o3 = c[i][j][3] + bn1;
                if (relu_out) {
                    o0 = fmaxf(o0, 0.f); o1 = fmaxf(o1, 0.f);
                    o2 = fmaxf(o2, 0.f); o3 = fmaxf(o3, 0.f);
                }
                if (r0 < NN)
                    *(__half2*)(outp + (size_t)r0 * DD + n) = __floats2half2_rn(o0, o1);
                if (r0 + 8 < NN)
                    *(__half2*)(outp + (size_t)(r0 + 8) * DD + n) = __floats2half2_rn(o2, o3);
            }
        }
    }
}

// ---------------- readout: fp16 activations ----------------
__global__ void k_readout(const float* __restrict__ Wm, const float* __restrict__ bm,
                          float* __restrict__ out) {
    int gw = (blockIdx.x * blockDim.x + threadIdx.x) >> 5;
    if (gw >= NN) return;
    int lane = threadIdx.x & 31;
    float acc = 0.f;
#pragma unroll
    for (int l = 0; l < 3; l++) {
        const uint2* xs2 = (const uint2*)(g_xs16 + (size_t)l * NN * DD);
        float4 v = h4tof4(xs2[(size_t)gw * 32 + lane]);
        float4 w = __ldg(&((const float4*)(Wm + l * 128))[lane]);
        acc += v.x * w.x + v.y * w.y + v.z * w.z + v.w * w.w;
    }
#pragma unroll
    for (int o = 16; o; o >>= 1) acc += __shfl_xor_sync(0xffffffffu, acc, o);
    if (lane == 0) {
        float z = acc + __ldg(bm);
        out[gw] = 1.0f / (1.0f + expf(-z));
    }
}

// ---------------- launch ----------------
extern "C" void kernel_launch(void* const* d_in, const int* in_sizes, int n_in,
                              void* d_out, int out_size) {
    const float* x  = (const float*)d_in[0];
    const int*   ei = (const int*)d_in[1];
    const float* W1[3] = {(const float*)d_in[3],  (const float*)d_in[7],  (const float*)d_in[11]};
    const float* b1[3] = {(const float*)d_in[4],  (const float*)d_in[8],  (const float*)d_in[12]};
    const float* W2[3] = {(const float*)d_in[5],  (const float*)d_in[9],  (const float*)d_in[13]};
    const float* b2[3] = {(const float*)d_in[6],  (const float*)d_in[10], (const float*)d_in[14]};
    const float* Wm = (const float*)d_in[15];
    const float* bm = (const float*)d_in[16];
    float* out = (float*)d_out;

    cudaFuncSetAttribute(k_mlp, cudaFuncAttributeMaxDynamicSharedMemorySize, SMEM_MLP);

    // prep (zero deg + x->fp16 + W split) then CSR build
    k_prep<<<(NN * DD / 4 + 255) / 256, 256>>>(x, W1[0], W2[0], W1[1], W2[1], W1[2], W2[2]);
    k_hist<<<(NE + 255) / 256, 256>>>(ei);
    k_scan1<<<NSB, SCAN_BLK>>>();
    k_scan3<<<NSB, SCAN_BLK>>>();
    k_scatter<<<(NE + 255) / 256, 256>>>(ei);

    const int AGG_BLOCKS = (NN * 32 + 255) / 256;   // 12500
    const int MLP_BLOCKS = (NN + 255) / 256;        // 391

    for (int l = 0; l < 3; l++) {
        k_agg<<<AGG_BLOCKS, 256>>>(l);
        k_mlp<<<MLP_BLOCKS, 256, SMEM_MLP>>>(b1[l], b2[l], l);
    }
    k_readout<<<AGG_BLOCKS, 256>>>(Wm, bm, out);
}

// round 17
// speedup vs baseline: 1.3678x; 1.0339x over previous
#include <cuda_runtime.h>
#include <cuda_bf16.h>
#include <cuda_fp16.h>
#include <stdint.h>
#include <math.h>

#define NN 100000
#define NE 1600000
#define DD 128
#define SCAN_BLK 1024
#define NSB ((NN + SCAN_BLK - 1) / SCAN_BLK)   // 98 scan blocks

// ---------------- scratch (device globals; no allocation) ----------------
__device__ alignas(16) __half g_agg16[(size_t)NN * DD];       // 25.6 MB (fp16 MLP input)
__device__ alignas(16) __half g_x16[(size_t)NN * DD];         // 25.6 MB (fp16 input copy)
__device__ alignas(16) __half g_xs16[(size_t)2 * NN * DD];    // 51.2 MB (fp16 layer0/1 outputs)
__device__ alignas(16) float  g_z3[NN];                       // 0.4 MB (layer2 readout partial)
__device__ alignas(16) __half g_wb[6 * 128 * 256];            // fp16 split weights [mat][n][k: hi|lo]
__device__ alignas(16) int   g_deg[NN];
__device__ alignas(16) int   g_cur[NN];
__device__ alignas(16) int   g_srcs[NE];
__device__ alignas(16) int   g_off[NN + 1];
__device__ alignas(16) int   g_bsum[NSB];

__device__ __forceinline__ uint32_t smem_u32(const void* p) {
    uint32_t a;
    asm("{ .reg .u64 t; cvta.to.shared.u64 t, %1; cvt.u32.u64 %0, t; }" : "=r"(a) : "l"(p));
    return a;
}
__device__ __forceinline__ void ldsm4(uint32_t& r0, uint32_t& r1, uint32_t& r2, uint32_t& r3, uint32_t addr) {
    asm volatile("ldmatrix.sync.aligned.m8n8.x4.shared.b16 {%0,%1,%2,%3}, [%4];"
                 : "=r"(r0), "=r"(r1), "=r"(r2), "=r"(r3) : "r"(addr));
}
__device__ __forceinline__ void mma16816(float* c, const uint32_t* a, const uint32_t* b) {
    asm volatile("mma.sync.aligned.m16n8k16.row.col.f32.f16.f16.f32 "
                 "{%0,%1,%2,%3}, {%4,%5,%6,%7}, {%8,%9}, {%0,%1,%2,%3};"
                 : "+f"(c[0]), "+f"(c[1]), "+f"(c[2]), "+f"(c[3])
                 : "r"(a[0]), "r"(a[1]), "r"(a[2]), "r"(a[3]), "r"(b[0]), "r"(b[1]));
}
// swizzled smem byte offset within a 512B row (W: k hi bytes 0-255, lo 256-511)
__device__ __forceinline__ uint32_t sws(int row, int kb) {
    return (uint32_t)(row * 512 + (kb ^ ((row & 7) << 4)));
}
// swizzled smem byte offset within a 256B fp16 row (A: 128 fp16)
__device__ __forceinline__ uint32_t swsA(int row, int kb) {
    return (uint32_t)(row * 256 + (kb ^ ((row & 7) << 4)));
}
__device__ __forceinline__ float4 h4tof4(uint2 u) {
    __half2 h0 = *(__half2*)&u.x, h1 = *(__half2*)&u.y;
    float2 f0 = __half22float2(h0), f1 = __half22float2(h1);
    return make_float4(f0.x, f0.y, f1.x, f1.y);
}
__device__ __forceinline__ uint32_t packh2(float a, float b) {
    __half2 h = __floats2half2_rn(a, b);
    return *(uint32_t*)&h;
}
// per-block int64-vs-int32 probe: high words of first 64 src entries all zero => int64
__device__ __forceinline__ int probe_is64(const int* __restrict__ ei32, int lane) {
    int nz = 0;
#pragma unroll
    for (int k = 0; k < 2; k++) {
        int w = __ldg(&ei32[2 * (lane + 32 * k) + 1]);
        nz |= (w != 0);
    }
    unsigned any = __ballot_sync(0xffffffffu, nz);
    return (any == 0u) ? 1 : 0;
}

// ---------------- prep: zero deg + x fp32->fp16 + weight split (one kernel) ----------------
__global__ void k_prep(const float* __restrict__ x,
                       const float* __restrict__ w0, const float* __restrict__ w1,
                       const float* __restrict__ w2, const float* __restrict__ w3,
                       const float* __restrict__ w4, const float* __restrict__ w5) {
    int i = blockIdx.x * blockDim.x + threadIdx.x;
    if (i < NN) g_deg[i] = 0;
    if (i < NN * DD / 4) {
        float4 v = ((const float4*)x)[i];
        ((__half2*)g_x16)[2 * i]     = __floats2half2_rn(v.x, v.y);
        ((__half2*)g_x16)[2 * i + 1] = __floats2half2_rn(v.z, v.w);
    }
    if (i < 6 * 128 * 128) {
        int mat = i >> 14;
        int k = (i >> 7) & 127;
        int n = i & 127;
        const float* W = (mat == 0) ? w0 : (mat == 1) ? w1 : (mat == 2) ? w2
                       : (mat == 3) ? w3 : (mat == 4) ? w4 : w5;
        float v = W[k * 128 + n];
        __half hi = __float2half_rn(v);
        __half lo = __float2half_rn(v - __half2float(hi));
        __half* dst = g_wb + (size_t)mat * 128 * 256 + (size_t)n * 256;
        dst[k] = hi;
        dst[128 + k] = lo;
    }
}

// ---------------- CSR build ----------------
__global__ void k_hist(const int* __restrict__ ei32) {
    int is64 = probe_is64(ei32, threadIdx.x & 31);
    int e = blockIdx.x * blockDim.x + threadIdx.x;
    if (e < NE) {
        unsigned d = is64 ? (unsigned)ei32[2 * (NE + e)] : (unsigned)ei32[NE + e];
        if (d < NN) atomicAdd(&g_deg[d], 1);
    }
}
__global__ void k_scan1() {
    __shared__ int ws[32];
    int i = blockIdx.x * SCAN_BLK + threadIdx.x;
    int v = (i < NN) ? g_deg[i] : 0;
    int s = v;
#pragma unroll
    for (int o = 16; o; o >>= 1) s += __shfl_xor_sync(0xffffffffu, s, o);
    if ((threadIdx.x & 31) == 0) ws[threadIdx.x >> 5] = s;
    __syncthreads();
    if (threadIdx.x < 32) {
        int t = ws[threadIdx.x];
#pragma unroll
        for (int o = 16; o; o >>= 1) t += __shfl_xor_sync(0xffffffffu, t, o);
        if (threadIdx.x == 0) g_bsum[blockIdx.x] = t;
    }
}
// block-local scan + cross-block base computed directly from g_bsum
__global__ void k_scan3() {
    __shared__ int wsum[32];
    __shared__ int gbase;
    int t = threadIdx.x;
    int i = blockIdx.x * SCAN_BLK + t;
    int v = (i < NN) ? g_deg[i] : 0;
    int lane = t & 31, wrp = t >> 5;
    int incl = v;
#pragma unroll
    for (int o = 1; o < 32; o <<= 1) {
        int u = __shfl_up_sync(0xffffffffu, incl, o);
        if (lane >= o) incl += u;
    }
    if (lane == 31) wsum[wrp] = incl;
    __syncthreads();
    if (wrp == 0) {
        int w = wsum[lane];
        int wincl = w;
#pragma unroll
        for (int o = 1; o < 32; o <<= 1) {
            int u = __shfl_up_sync(0xffffffffu, wincl, o);
            if (lane >= o) wincl += u;
        }
        wsum[lane] = wincl - w;
        int mybase = 0, total = 0;
        for (int j = lane; j < NSB; j += 32) {
            int b = g_bsum[j];
            total += b;
            if (j < blockIdx.x) mybase += b;
        }
#pragma unroll
        for (int o = 16; o; o >>= 1) {
            mybase += __shfl_xor_sync(0xffffffffu, mybase, o);
            total  += __shfl_xor_sync(0xffffffffu, total, o);
        }
        if (lane == 0) {
            gbase = mybase;
            if (blockIdx.x == NSB - 1) g_off[NN] = total;
        }
    }
    __syncthreads();
    if (i < NN) {
        int off = gbase + wsum[wrp] + incl - v;
        g_off[i] = off;
        g_cur[i] = off;
    }
}
__global__ void k_scatter(const int* __restrict__ ei32) {
    int is64 = probe_is64(ei32, threadIdx.x & 31);
    int e = blockIdx.x * blockDim.x + threadIdx.x;
    if (e < NE) {
        unsigned d    = is64 ? (unsigned)ei32[2 * (NE + e)] : (unsigned)ei32[NE + e];
        unsigned srcv = is64 ? (unsigned)ei32[2 * e]        : (unsigned)ei32[e];
        if (d < NN && srcv < NN) {
            int pos = atomicAdd(&g_cur[d], 1);
            g_srcs[pos] = (int)srcv;
        }
    }
}

// ---------------- aggregation: fp16 gather, fp32 accumulate, fp16 out ----------------
__global__ void k_agg(int layer) {
    int gw = (blockIdx.x * blockDim.x + threadIdx.x) >> 5;
    if (gw >= NN) return;
    int lane = threadIdx.x & 31;
    const __half* xin = (layer == 0) ? g_x16 : (g_xs16 + (size_t)(layer - 1) * NN * DD);
    const uint2* x2 = (const uint2*)xin;   // 4 halves per lane, 32 lanes = 256B row

    float4 acc = h4tof4(x2[(size_t)gw * 32 + lane]);
    int j = g_off[gw];
    int end = g_off[gw + 1];
    for (; j + 3 < end; j += 4) {
        int s0 = g_srcs[j], s1 = g_srcs[j + 1], s2 = g_srcs[j + 2], s3 = g_srcs[j + 3];
        uint2 ua = __ldg(&x2[(size_t)s0 * 32 + lane]);
        uint2 ub = __ldg(&x2[(size_t)s1 * 32 + lane]);
        uint2 uc = __ldg(&x2[(size_t)s2 * 32 + lane]);
        uint2 ud = __ldg(&x2[(size_t)s3 * 32 + lane]);
        float4 a = h4tof4(ua), b = h4tof4(ub), c = h4tof4(uc), d = h4tof4(ud);
        acc.x += (a.x + b.x) + (c.x + d.x);
        acc.y += (a.y + b.y) + (c.y + d.y);
        acc.z += (a.z + b.z) + (c.z + d.z);
        acc.w += (a.w + b.w) + (c.w + d.w);
    }
    for (; j < end; j++) {
        float4 a = h4tof4(__ldg(&x2[(size_t)g_srcs[j] * 32 + lane]));
        acc.x += a.x; acc.y += a.y; acc.z += a.z; acc.w += a.w;
    }
    uint2 o;
    *(__half2*)&o.x = __floats2half2_rn(acc.x, acc.y);
    *(__half2*)&o.y = __floats2half2_rn(acc.z, acc.w);
    ((uint2*)g_agg16)[(size_t)gw * 32 + lane] = o;
}

// ---------------- f16 mma.sync MLP: 256x128 tile per CTA, 2-term W split ----------------
// smem: A @0 (256 rows x 256B = 64KB), W1 @65536 (64KB), W2 @131072 (64KB)
#define SW1_OFF 65536u
#define SW2_OFF 131072u
#define SMEM_MLP 196608

__global__ __launch_bounds__(256)
void k_mlp(const float* __restrict__ b1, const float* __restrict__ b2,
           const float* __restrict__ Wm, int layer)
{
    extern __shared__ char smem[];
    const uint32_t sa = smem_u32(smem);
    const int tid = threadIdx.x, wid = tid >> 5, lane = tid & 31;
    const int base = blockIdx.x * 256;
    const int wm = wid & 3, wn = wid >> 2;
    const int m0w = wm * 64;            // warp's 64 rows
    const int ncol0 = wn * 64;          // warp's 64 cols
    const int lr = lane & 7, grp = lane >> 3;
    const __half* wb1 = g_wb + (size_t)(layer * 2)     * 128 * 256;
    const __half* wb2 = g_wb + (size_t)(layer * 2 + 1) * 128 * 256;

    // ---- A tile: raw fp16 copy from g_agg16 into swizzled smem (exact) ----
    {
        const uint2* in2 = (const uint2*)g_agg16;
        int kb = lane * 8;
#pragma unroll 4
        for (int it = 0; it < 32; it++) {
            int m = wid + it * 8;         // 0..255
            int node = base + m;
            uint2 v = make_uint2(0u, 0u);
            if (node < NN) v = in2[(size_t)node * 32 + lane];
            *(uint2*)(smem + swsA(m, kb)) = v;
        }
    }
    // ---- W1/W2 (fp16 hi|lo, 512B rows) into swizzled smem ----
    {
        int kb = lane * 16;
#pragma unroll 4
        for (int it = 0; it < 16; it++) {
            int n = wid + it * 8;
            uint4 r1 = ((const uint4*)(wb1 + (size_t)n * 256))[lane];
            uint4 r2 = ((const uint4*)(wb2 + (size_t)n * 256))[lane];
            uint32_t o = sws(n, kb);
            *(uint4*)(smem + SW1_OFF + o) = r1;
            *(uint4*)(smem + SW2_OFF + o) = r2;
        }
    }
    __syncthreads();

    const int arow = lr + ((grp & 1) << 3);
    const int akadd = (grp & 2) ? 16 : 0;
    const int brow = lr + ((grp & 2) << 2);
    const int bkadd = (grp & 1) ? 16 : 0;
    const uint32_t lxor = (uint32_t)(lr << 4);
    uint32_t abase[4], bbase[4];
#pragma unroll
    for (int i = 0; i < 4; i++) abase[i] = sa + (uint32_t)((m0w + 16 * i + arow) * 256);
#pragma unroll
    for (int j = 0; j < 4; j++) bbase[j] = (uint32_t)((ncol0 + 16 * j + brow) * 512);

    float c[4][8][4];

#pragma unroll 1
    for (int g = 0; g < 2; g++) {
        const uint32_t woff = sa + (g == 0 ? SW1_OFF : SW2_OFF);
#pragma unroll
        for (int i = 0; i < 4; i++)
#pragma unroll
            for (int j = 0; j < 8; j++)
#pragma unroll
                for (int q = 0; q < 4; q++) c[i][j][q] = 0.f;

        // 2 W-split terms x 8 k-steps
#pragma unroll 1
        for (int t = 0; t < 2; t++) {
            const int bkoff = (t == 1) ? 256 : 0;
#pragma unroll
            for (int ks = 0; ks < 8; ks++) {
                const int kb = ks * 32;
                uint32_t fa[4][4], fb[8][2];
#pragma unroll
                for (int i = 0; i < 4; i++)
                    ldsm4(fa[i][0], fa[i][1], fa[i][2], fa[i][3],
                          abase[i] + (uint32_t)((kb + akadd) ^ lxor));
#pragma unroll
                for (int jj = 0; jj < 4; jj++) {
                    uint32_t r0, r1, r2, r3;
                    ldsm4(r0, r1, r2, r3,
                          woff + bbase[jj] + (uint32_t)((kb + bkoff + bkadd) ^ lxor));
                    fb[2 * jj][0] = r0; fb[2 * jj][1] = r1;
                    fb[2 * jj + 1][0] = r2; fb[2 * jj + 1][1] = r3;
                }
#pragma unroll
                for (int i = 0; i < 4; i++)
#pragma unroll
                    for (int j = 0; j < 8; j++)
                        mma16816(c[i][j], fa[i], fb[j]);
            }
        }

        if (g == 0) {
            // epilogue 1: bias + relu, store h (fp16) back into A smem
            __syncthreads();
#pragma unroll
            for (int j = 0; j < 8; j++) {
                int n = ncol0 + 8 * j + 2 * (lane & 3);
                float bn0 = __ldg(&b1[n]), bn1 = __ldg(&b1[n + 1]);
#pragma unroll
                for (int i = 0; i < 4; i++) {
                    int r0 = m0w + 16 * i + (lane >> 2);
                    float h0 = fmaxf(c[i][j][0] + bn0, 0.f);
                    float h1 = fmaxf(c[i][j][1] + bn1, 0.f);
                    float h2 = fmaxf(c[i][j][2] + bn0, 0.f);
                    float h3 = fmaxf(c[i][j][3] + bn1, 0.f);
                    *(uint32_t*)(smem + swsA(r0, 2 * n))     = packh2(h0, h1);
                    *(uint32_t*)(smem + swsA(r0 + 8, 2 * n)) = packh2(h2, h3);
                }
            }
            __syncthreads();
        }
    }

    if (layer < 2) {
        // ---- epilogue 2: bias + relu, write fp16 g_xs16[layer] ----
        __half* outp = g_xs16 + (size_t)layer * NN * DD;
#pragma unroll
        for (int j = 0; j < 8; j++) {
            int n = ncol0 + 8 * j + 2 * (lane & 3);
            float bn0 = __ldg(&b2[n]), bn1 = __ldg(&b2[n + 1]);
#pragma unroll
            for (int i = 0; i < 4; i++) {
                int r0 = base + m0w + 16 * i + (lane >> 2);
                float o0 = fmaxf(c[i][j][0] + bn0, 0.f);
                float o1 = fmaxf(c[i][j][1] + bn1, 0.f);
                float o2 = fmaxf(c[i][j][2] + bn0, 0.f);
                float o3 = fmaxf(c[i][j][3] + bn1, 0.f);
                if (r0 < NN)
                    *(__half2*)(outp + (size_t)r0 * DD + n) = __floats2half2_rn(o0, o1);
                if (r0 + 8 < NN)
                    *(__half2*)(outp + (size_t)(r0 + 8) * DD + n) = __floats2half2_rn(o2, o3);
            }
        }
    } else {
        // ---- layer 2: fuse x3 . Wm[256:384] in registers, write only z3[node] ----
        float part[4][2];
#pragma unroll
        for (int i = 0; i < 4; i++) { part[i][0] = 0.f; part[i][1] = 0.f; }
#pragma unroll
        for (int j = 0; j < 8; j++) {
            int n = ncol0 + 8 * j + 2 * (lane & 3);
            float bn0 = __ldg(&b2[n]), bn1 = __ldg(&b2[n + 1]);
            float w0 = __ldg(&Wm[256 + n]), w1 = __ldg(&Wm[256 + n + 1]);
#pragma unroll
            for (int i = 0; i < 4; i++) {
                part[i][0] += (c[i][j][0] + bn0) * w0 + (c[i][j][1] + bn1) * w1;
                part[i][1] += (c[i][j][2] + bn0) * w0 + (c[i][j][3] + bn1) * w1;
            }
        }
        __syncthreads();                 // A region free (GEMM2 reads done)
        float* P = (float*)smem;         // [256 rows][9] floats = 9216 B
        int slot = wn * 4 + (lane & 3);
#pragma unroll
        for (int i = 0; i < 4; i++)
#pragma unroll
            for (int s = 0; s < 2; s++) {
                int row = m0w + 16 * i + 8 * s + (lane >> 2);
                P[row * 9 + slot] = part[i][s];
            }
        __syncthreads();
        int row = tid;                   // 256 threads, 256 rows
        float z = 0.f;
#pragma unroll
        for (int s = 0; s < 8; s++) z += P[row * 9 + s];
        int node = base + row;
        if (node < NN) g_z3[node] = z;
    }
}

// ---------------- readout: x1/x2 (fp16) + z3 partial ----------------
__global__ void k_readout(const float* __restrict__ Wm, const float* __restrict__ bm,
                          float* __restrict__ out) {
    int gw = (blockIdx.x * blockDim.x + threadIdx.x) >> 5;
    if (gw >= NN) return;
    int lane = threadIdx.x & 31;
    float acc = 0.f;
#pragma unroll
    for (int l = 0; l < 2; l++) {
        const uint2* xs2 = (const uint2*)(g_xs16 + (size_t)l * NN * DD);
        float4 v = h4tof4(xs2[(size_t)gw * 32 + lane]);
        float4 w = __ldg(&((const float4*)(Wm + l * 128))[lane]);
        acc += v.x * w.x + v.y * w.y + v.z * w.z + v.w * w.w;
    }
#pragma unroll
    for (int o = 16; o; o >>= 1) acc += __shfl_xor_sync(0xffffffffu, acc, o);
    if (lane == 0) {
        float z = acc + g_z3[gw] + __ldg(bm);
        out[gw] = 1.0f / (1.0f + expf(-z));
    }
}

// ---------------- launch ----------------
extern "C" void kernel_launch(void* const* d_in, const int* in_sizes, int n_in,
                              void* d_out, int out_size) {
    const float* x  = (const float*)d_in[0];
    const int*   ei = (const int*)d_in[1];
    const float* W1[3] = {(const float*)d_in[3],  (const float*)d_in[7],  (const float*)d_in[11]};
    const float* b1[3] = {(const float*)d_in[4],  (const float*)d_in[8],  (const float*)d_in[12]};
    const float* W2[3] = {(const float*)d_in[5],  (const float*)d_in[9],  (const float*)d_in[13]};
    const float* b2[3] = {(const float*)d_in[6],  (const float*)d_in[10], (const float*)d_in[14]};
    const float* Wm = (const float*)d_in[15];
    const float* bm = (const float*)d_in[16];
    float* out = (float*)d_out;

    cudaFuncSetAttribute(k_mlp, cudaFuncAttributeMaxDynamicSharedMemorySize, SMEM_MLP);

    // prep (zero deg + x->fp16 + W split) then CSR build
    k_prep<<<(NN * DD / 4 + 255) / 256, 256>>>(x, W1[0], W2[0], W1[1], W2[1], W1[2], W2[2]);
    k_hist<<<(NE + 255) / 256, 256>>>(ei);
    k_scan1<<<NSB, SCAN_BLK>>>();
    k_scan3<<<NSB, SCAN_BLK>>>();
    k_scatter<<<(NE + 255) / 256, 256>>>(ei);

    const int AGG_BLOCKS = (NN * 32 + 255) / 256;   // 12500
    const int MLP_BLOCKS = (NN + 255) / 256;        // 391

    for (int l = 0; l < 3; l++) {
        k_agg<<<AGG_BLOCKS, 256>>>(l);
        k_mlp<<<MLP_BLOCKS, 256, SMEM_MLP>>>(b1[l], b2[l], Wm, l);
    }
    k_readout<<<AGG_BLOCKS, 256>>>(Wm, bm, out);
}